// round 1
// baseline (speedup 1.0000x reference)
#include <cuda_runtime.h>
#include <cuda_bf16.h>
#include <math.h>

// Problem constants
#define BB 2
#define NN 48
#define DD 256
#define HH 8
#define DKV 64
#define FFD 1024
#define LL 4
#define PDD 32
#define NFD 20
#define NED 5
#define SS 2352           // NN + NN*NN
#define BS 4704           // BB*SS

// -------------------- scratch (device globals; no allocation) --------------------
__device__ float g_pos[BB * NN * PDD];
__device__ float g_x[BS * DD];
__device__ float g_q[BS * HH * DKV];
__device__ float g_k[BS * HH * DKV];
__device__ float g_v[BS * HH * DKV];
__device__ float g_attn[BS * HH * DKV];
__device__ float g_t[BS * DD];
__device__ float g_ff[BS * FFD];

// -------------------- pos = perm @ posenc --------------------
// grid: BB*NN blocks, 32 threads (one per PD dim)
__global__ void pos_kernel(const float* __restrict__ perm, float* __restrict__ pos)
{
    int row = blockIdx.x;            // b*NN + i
    int d = threadIdx.x;             // 0..31
    const float* pr = perm + (size_t)row * NN;
    float freq = expf(-logf(10000.f) * (float)(d & ~1) / (float)PDD);
    float s = 0.f;
    #pragma unroll 8
    for (int j = 0; j < NN; j++) {
        float ang = (float)j * freq;
        float pe = (d & 1) ? cosf(ang) : sinf(ang);
        s += pr[j] * pe;
    }
    pos[row * PDD + d] = s;
}

// -------------------- token embedding --------------------
// grid: BS blocks, 256 threads (one per D dim)
__global__ void embed_kernel(const float* __restrict__ ge, const float* __restrict__ pos,
                             const float* __restrict__ pnw, const float* __restrict__ pnb,
                             const float* __restrict__ pew, const float* __restrict__ peb,
                             float* __restrict__ x)
{
    int tok = blockIdx.x;
    int b = tok / SS;
    int r = tok % SS;
    int d = threadIdx.x;
    __shared__ float pi[PDD];
    __shared__ float pj[PDD];

    if (r < NN) {
        if (d < PDD) pi[d] = pos[(b * NN + r) * PDD + d];
        __syncthreads();
        float s = ge[b * DD + d] + pnb[d];
        #pragma unroll
        for (int p = 0; p < PDD; p++) s += pi[p] * pnw[p * DD + d];
        x[(size_t)tok * DD + d] = s;
    } else {
        int e = r - NN;
        int i = e / NN, j = e % NN;
        if (d < PDD) pi[d] = pos[(b * NN + i) * PDD + d];
        else if (d < 2 * PDD) pj[d - PDD] = pos[(b * NN + j) * PDD + (d - PDD)];
        __syncthreads();
        float s = ge[b * DD + d] + peb[d];
        #pragma unroll
        for (int p = 0; p < PDD; p++) s += pi[p] * pew[p * DD + d];
        #pragma unroll
        for (int p = 0; p < PDD; p++) s += pj[p] * pew[(PDD + p) * DD + d];
        x[(size_t)tok * DD + d] = s;
    }
}

// -------------------- tiled fp32 GEMM: C = act(A @ W + bias) --------------------
// A: MxK row-major, W: KxNc row-major (K%16==0, Nc%64==0), M bounds-checked.
// 64x64 tile, BK=16, 256 threads, 4x4 per thread.
__global__ void gemm_bias_kernel(const float* __restrict__ A, const float* __restrict__ W,
                                 const float* __restrict__ bias, float* __restrict__ C,
                                 int M, int K, int Nc, int relu)
{
    __shared__ float As[16][68];   // padded: [k][m]
    __shared__ float Bs[16][64];   // [k][n]
    int tid = threadIdx.x;
    int tx = tid & 15;             // 0..15 -> col group
    int ty = tid >> 4;             // 0..15 -> row group
    int row0 = blockIdx.y * 64;
    int col0 = blockIdx.x * 64;

    int a_row  = tid >> 2;         // 0..63
    int a_part = (tid & 3) * 4;    // 0,4,8,12
    int b_row  = tid >> 4;         // 0..15
    int b_col  = (tid & 15) * 4;   // 0..60

    float acc[4][4];
    #pragma unroll
    for (int i = 0; i < 4; i++)
        #pragma unroll
        for (int j = 0; j < 4; j++) acc[i][j] = 0.f;

    for (int k0 = 0; k0 < K; k0 += 16) {
        int gr = row0 + a_row;
        float4 av = make_float4(0.f, 0.f, 0.f, 0.f);
        if (gr < M) av = *(const float4*)(A + (size_t)gr * K + k0 + a_part);
        As[a_part + 0][a_row] = av.x;
        As[a_part + 1][a_row] = av.y;
        As[a_part + 2][a_row] = av.z;
        As[a_part + 3][a_row] = av.w;

        float4 bv = *(const float4*)(W + (size_t)(k0 + b_row) * Nc + col0 + b_col);
        *(float4*)&Bs[b_row][b_col] = bv;
        __syncthreads();

        #pragma unroll
        for (int k = 0; k < 16; k++) {
            float a0 = As[k][ty * 4 + 0];
            float a1 = As[k][ty * 4 + 1];
            float a2 = As[k][ty * 4 + 2];
            float a3 = As[k][ty * 4 + 3];
            float4 b4 = *(const float4*)&Bs[k][tx * 4];
            acc[0][0] += a0 * b4.x; acc[0][1] += a0 * b4.y; acc[0][2] += a0 * b4.z; acc[0][3] += a0 * b4.w;
            acc[1][0] += a1 * b4.x; acc[1][1] += a1 * b4.y; acc[1][2] += a1 * b4.z; acc[1][3] += a1 * b4.w;
            acc[2][0] += a2 * b4.x; acc[2][1] += a2 * b4.y; acc[2][2] += a2 * b4.z; acc[2][3] += a2 * b4.w;
            acc[3][0] += a3 * b4.x; acc[3][1] += a3 * b4.y; acc[3][2] += a3 * b4.z; acc[3][3] += a3 * b4.w;
        }
        __syncthreads();
    }

    int col = col0 + tx * 4;
    float4 bsv = *(const float4*)(bias + col);
    #pragma unroll
    for (int i = 0; i < 4; i++) {
        int r = row0 + ty * 4 + i;
        if (r < M) {
            float4 v;
            v.x = acc[i][0] + bsv.x;
            v.y = acc[i][1] + bsv.y;
            v.z = acc[i][2] + bsv.z;
            v.w = acc[i][3] + bsv.w;
            if (relu) {
                v.x = fmaxf(v.x, 0.f); v.y = fmaxf(v.y, 0.f);
                v.z = fmaxf(v.z, 0.f); v.w = fmaxf(v.w, 0.f);
            }
            *(float4*)(C + (size_t)r * Nc + col) = v;
        }
    }
}

// -------------------- flash attention (fp32, warp per query row) --------------------
// grid: (SS/8, HH, BB), block 256 (8 warps)
__global__ void attn_kernel(const float* __restrict__ Q, const float* __restrict__ Kmat,
                            const float* __restrict__ V, float* __restrict__ O)
{
    int b = blockIdx.z, h = blockIdx.y;
    int warp = threadIdx.x >> 5, lane = threadIdx.x & 31;
    int q = blockIdx.x * 8 + warp;

    __shared__ float qs[8][64];
    __shared__ float ps[8][32];

    const float* qp = Q + ((size_t)(b * SS + q) * 512 + h * 64);
    const float* kb = Kmat + ((size_t)b * SS * 512 + h * 64);
    const float* vb = V + ((size_t)b * SS * 512 + h * 64);

    ((float2*)qs[warp])[lane] = ((const float2*)qp)[lane];
    __syncwarp();

    float m = -1e30f, l = 0.f;
    float accx = 0.f, accy = 0.f;
    const float scale = 0.125f;   // 1/sqrt(64)

    for (int c0 = 0; c0 < SS; c0 += 32) {
        int k = c0 + lane;
        float s = -1e30f;
        if (k < SS) {
            const float* kr = kb + (size_t)k * 512;
            float dot = 0.f;
            #pragma unroll
            for (int d4 = 0; d4 < 16; d4++) {
                float4 kv = ((const float4*)kr)[d4];
                dot += qs[warp][d4 * 4 + 0] * kv.x + qs[warp][d4 * 4 + 1] * kv.y
                     + qs[warp][d4 * 4 + 2] * kv.z + qs[warp][d4 * 4 + 3] * kv.w;
            }
            s = dot * scale;
        }
        float cm = s;
        #pragma unroll
        for (int o = 16; o; o >>= 1) cm = fmaxf(cm, __shfl_xor_sync(0xffffffffu, cm, o));
        float mnew = fmaxf(m, cm);
        float corr = expf(m - mnew);
        float p = expf(s - mnew);
        float psum = p;
        #pragma unroll
        for (int o = 16; o; o >>= 1) psum += __shfl_xor_sync(0xffffffffu, psum, o);
        l = l * corr + psum;
        accx *= corr; accy *= corr;
        m = mnew;

        ps[warp][lane] = p;
        __syncwarp();
        int tmax = min(32, SS - c0);
        #pragma unroll 8
        for (int t = 0; t < tmax; t++) {
            float pt = ps[warp][t];
            float2 vv = *(const float2*)(vb + (size_t)(c0 + t) * 512 + 2 * lane);
            accx += pt * vv.x; accy += pt * vv.y;
        }
        __syncwarp();
    }
    float inv = 1.f / l;
    float2 o2; o2.x = accx * inv; o2.y = accy * inv;
    *(float2*)(O + ((size_t)(b * SS + q) * 512 + h * 64 + 2 * lane)) = o2;
}

// -------------------- x = LayerNorm(x + h) --------------------
// grid: BS blocks, 256 threads
__global__ void add_ln_kernel(float* __restrict__ x, const float* __restrict__ h,
                              const float* __restrict__ g, const float* __restrict__ bb)
{
    int row = blockIdx.x, t = threadIdx.x;
    float v = x[(size_t)row * DD + t] + h[(size_t)row * DD + t];
    float s1 = v, s2 = v * v;
    #pragma unroll
    for (int o = 16; o; o >>= 1) {
        s1 += __shfl_xor_sync(0xffffffffu, s1, o);
        s2 += __shfl_xor_sync(0xffffffffu, s2, o);
    }
    __shared__ float r1[8], r2[8];
    int w = t >> 5, ln = t & 31;
    if (ln == 0) { r1[w] = s1; r2[w] = s2; }
    __syncthreads();
    if (w == 0) {
        float a = (ln < 8) ? r1[ln] : 0.f;
        float c = (ln < 8) ? r2[ln] : 0.f;
        #pragma unroll
        for (int o = 4; o; o >>= 1) {
            a += __shfl_xor_sync(0xffffffffu, a, o);
            c += __shfl_xor_sync(0xffffffffu, c, o);
        }
        if (ln == 0) { r1[0] = a; r2[0] = c; }
    }
    __syncthreads();
    float mean = r1[0] * (1.f / 256.f);
    float var = r2[0] * (1.f / 256.f) - mean * mean;
    float rstd = rsqrtf(var + 1e-5f);
    x[(size_t)row * DD + t] = (v - mean) * rstd * g[t] + bb[t];
}

// -------------------- output heads --------------------
// node logits: grid BB*NN, 32 threads (20 active)
__global__ void node_out_kernel(const float* __restrict__ x, const float* __restrict__ w,
                                const float* __restrict__ bias, float* __restrict__ out)
{
    int idx = blockIdx.x;            // b*NN + i
    int b = idx / NN, i = idx % NN;
    int f = threadIdx.x;
    if (f >= NFD) return;
    const float* xr = x + (size_t)(b * SS + i) * DD;
    float s = 0.f;
    #pragma unroll 8
    for (int d = 0; d < DD; d++) s += xr[d] * w[d * NFD + f];
    out[(size_t)idx * NFD + f] = s + bias[f];
}

// edge logits (symmetrized): grid BB*NN*NN, 32 threads (5 active)
__global__ void edge_out_kernel(const float* __restrict__ x, const float* __restrict__ w,
                                const float* __restrict__ bias, float* __restrict__ out)
{
    int idx = blockIdx.x;            // b*NN*NN + i*NN + j
    int b = idx / (NN * NN);
    int r = idx % (NN * NN);
    int i = r / NN, j = r % NN;
    int c = threadIdx.x;
    if (c >= NED) return;
    const float* xi = x + (size_t)(b * SS + NN + i * NN + j) * DD;
    const float* xj = x + (size_t)(b * SS + NN + j * NN + i) * DD;
    float s = 0.f;
    #pragma unroll 8
    for (int d = 0; d < DD; d++) s += (xi[d] + xj[d]) * w[d * NED + c];
    out[(size_t)idx * NED + c] = 0.5f * s + bias[c];
}

// -------------------- host orchestration --------------------
static inline float* sym_addr(const void* sym)
{
    void* p = nullptr;
    cudaGetSymbolAddress(&p, sym);
    return (float*)p;
}

extern "C" void kernel_launch(void* const* d_in, const int* in_sizes, int n_in,
                              void* d_out, int out_size)
{
    (void)in_sizes; (void)n_in; (void)out_size;
    const float* graph_emb = (const float*)d_in[0];
    const float* perm      = (const float*)d_in[1];
    // d_in[2] = mask (all true) — masking is a no-op
    const float* pnw = (const float*)d_in[3];
    const float* pnb = (const float*)d_in[4];
    const float* pew = (const float*)d_in[5];
    const float* peb = (const float*)d_in[6];
    const float* now_ = (const float*)d_in[7];
    const float* nob = (const float*)d_in[8];
    const float* eow = (const float*)d_in[9];
    const float* eob = (const float*)d_in[10];
    const float* Wq = (const float*)d_in[11];
    const float* bq = (const float*)d_in[12];
    const float* Wk = (const float*)d_in[13];
    const float* bk = (const float*)d_in[14];
    const float* Wv = (const float*)d_in[15];
    const float* bv = (const float*)d_in[16];
    const float* Wo = (const float*)d_in[17];
    const float* bo = (const float*)d_in[18];
    const float* W1 = (const float*)d_in[19];
    const float* b1 = (const float*)d_in[20];
    const float* W2 = (const float*)d_in[21];
    const float* b2 = (const float*)d_in[22];
    const float* ln1g = (const float*)d_in[23];
    const float* ln1b = (const float*)d_in[24];
    const float* ln2g = (const float*)d_in[25];
    const float* ln2b = (const float*)d_in[26];

    float* px   = sym_addr(g_x);
    float* ppos = sym_addr(g_pos);
    float* pq   = sym_addr(g_q);
    float* pk   = sym_addr(g_k);
    float* pv   = sym_addr(g_v);
    float* pat  = sym_addr(g_attn);
    float* pt   = sym_addr(g_t);
    float* pff  = sym_addr(g_ff);

    const int MROWS = BS;                 // 4704
    const int MTILES = (MROWS + 63) / 64; // 74

    pos_kernel<<<BB * NN, 32>>>(perm, ppos);
    embed_kernel<<<BS, 256>>>(graph_emb, ppos, pnw, pnb, pew, peb, px);

    for (int l = 0; l < LL; l++) {
        const float* wq = Wq + (size_t)l * DD * 512;
        const float* wk = Wk + (size_t)l * DD * 512;
        const float* wv = Wv + (size_t)l * DD * 512;
        const float* wo = Wo + (size_t)l * 512 * DD;
        const float* w1 = W1 + (size_t)l * DD * FFD;
        const float* w2 = W2 + (size_t)l * FFD * DD;

        gemm_bias_kernel<<<dim3(512 / 64, MTILES), 256>>>(px, wq, bq + l * 512, pq, MROWS, DD, 512, 0);
        gemm_bias_kernel<<<dim3(512 / 64, MTILES), 256>>>(px, wk, bk + l * 512, pk, MROWS, DD, 512, 0);
        gemm_bias_kernel<<<dim3(512 / 64, MTILES), 256>>>(px, wv, bv + l * 512, pv, MROWS, DD, 512, 0);

        attn_kernel<<<dim3(SS / 8, HH, BB), 256>>>(pq, pk, pv, pat);

        gemm_bias_kernel<<<dim3(DD / 64, MTILES), 256>>>(pat, wo, bo + l * DD, pt, MROWS, 512, DD, 0);
        add_ln_kernel<<<BS, 256>>>(px, pt, ln1g + l * DD, ln1b + l * DD);

        gemm_bias_kernel<<<dim3(FFD / 64, MTILES), 256>>>(px, w1, b1 + l * FFD, pff, MROWS, DD, FFD, 1);
        gemm_bias_kernel<<<dim3(DD / 64, MTILES), 256>>>(pff, w2, b2 + l * DD, pt, MROWS, FFD, DD, 0);
        add_ln_kernel<<<BS, 256>>>(px, pt, ln2g + l * DD, ln2b + l * DD);
    }

    float* out = (float*)d_out;
    node_out_kernel<<<BB * NN, 32>>>(px, now_, nob, out);
    edge_out_kernel<<<BB * NN * NN, 32>>>(px, eow, eob, out + BB * NN * NFD);
}

// round 2
// speedup vs baseline: 6.4406x; 6.4406x over previous
#include <cuda_runtime.h>
#include <cuda_bf16.h>
#include <math.h>

// Problem constants
#define BB 2
#define NN 48
#define DD 256
#define HH 8
#define DKV 64
#define FFD 1024
#define LL 4
#define PDD 32
#define NFD 20
#define NED 5
#define SS 2352           // NN + NN*NN
#define BS 4704           // BB*SS
#define QT 37             // ceil(SS/64) query tiles

// -------------------- scratch (device globals; no allocation) --------------------
__device__ float g_pos[BB * NN * PDD];
__device__ float g_x[BS * DD];
__device__ float g_q[BS * HH * DKV];
__device__ float g_k[BS * HH * DKV];
__device__ float g_v[BS * HH * DKV];
__device__ float g_attn[BS * HH * DKV];
__device__ float g_t[BS * DD];
__device__ float g_ff[BS * FFD];

// -------------------- pos = perm @ posenc --------------------
__global__ void pos_kernel(const float* __restrict__ perm, float* __restrict__ pos)
{
    int row = blockIdx.x;            // b*NN + i
    int d = threadIdx.x;             // 0..31
    const float* pr = perm + (size_t)row * NN;
    float freq = expf(-logf(10000.f) * (float)(d & ~1) / (float)PDD);
    float s = 0.f;
    #pragma unroll 8
    for (int j = 0; j < NN; j++) {
        float ang = (float)j * freq;
        float pe = (d & 1) ? cosf(ang) : sinf(ang);
        s += pr[j] * pe;
    }
    pos[row * PDD + d] = s;
}

// -------------------- token embedding --------------------
__global__ void embed_kernel(const float* __restrict__ ge, const float* __restrict__ pos,
                             const float* __restrict__ pnw, const float* __restrict__ pnb,
                             const float* __restrict__ pew, const float* __restrict__ peb,
                             float* __restrict__ x)
{
    int tok = blockIdx.x;
    int b = tok / SS;
    int r = tok % SS;
    int d = threadIdx.x;
    __shared__ float pi[PDD];
    __shared__ float pj[PDD];

    if (r < NN) {
        if (d < PDD) pi[d] = pos[(b * NN + r) * PDD + d];
        __syncthreads();
        float s = ge[b * DD + d] + pnb[d];
        #pragma unroll
        for (int p = 0; p < PDD; p++) s += pi[p] * pnw[p * DD + d];
        x[(size_t)tok * DD + d] = s;
    } else {
        int e = r - NN;
        int i = e / NN, j = e % NN;
        if (d < PDD) pi[d] = pos[(b * NN + i) * PDD + d];
        else if (d < 2 * PDD) pj[d - PDD] = pos[(b * NN + j) * PDD + (d - PDD)];
        __syncthreads();
        float s = ge[b * DD + d] + peb[d];
        #pragma unroll
        for (int p = 0; p < PDD; p++) s += pi[p] * pew[p * DD + d];
        #pragma unroll
        for (int p = 0; p < PDD; p++) s += pj[p] * pew[(PDD + p) * DD + d];
        x[(size_t)tok * DD + d] = s;
    }
}

// -------------------- tiled fp32 GEMM: C = act(A @ W + bias) --------------------
__global__ void gemm_bias_kernel(const float* __restrict__ A, const float* __restrict__ W,
                                 const float* __restrict__ bias, float* __restrict__ C,
                                 int M, int K, int Nc, int relu)
{
    __shared__ float As[16][68];   // [k][m]
    __shared__ float Bs[16][64];   // [k][n]
    int tid = threadIdx.x;
    int tx = tid & 15;
    int ty = tid >> 4;
    int row0 = blockIdx.y * 64;
    int col0 = blockIdx.x * 64;

    int a_row  = tid >> 2;
    int a_part = (tid & 3) * 4;
    int b_row  = tid >> 4;
    int b_col  = (tid & 15) * 4;

    float acc[4][4];
    #pragma unroll
    for (int i = 0; i < 4; i++)
        #pragma unroll
        for (int j = 0; j < 4; j++) acc[i][j] = 0.f;

    for (int k0 = 0; k0 < K; k0 += 16) {
        int gr = row0 + a_row;
        float4 av = make_float4(0.f, 0.f, 0.f, 0.f);
        if (gr < M) av = *(const float4*)(A + (size_t)gr * K + k0 + a_part);
        As[a_part + 0][a_row] = av.x;
        As[a_part + 1][a_row] = av.y;
        As[a_part + 2][a_row] = av.z;
        As[a_part + 3][a_row] = av.w;

        float4 bv = *(const float4*)(W + (size_t)(k0 + b_row) * Nc + col0 + b_col);
        *(float4*)&Bs[b_row][b_col] = bv;
        __syncthreads();

        #pragma unroll
        for (int k = 0; k < 16; k++) {
            float a0 = As[k][ty * 4 + 0];
            float a1 = As[k][ty * 4 + 1];
            float a2 = As[k][ty * 4 + 2];
            float a3 = As[k][ty * 4 + 3];
            float4 b4 = *(const float4*)&Bs[k][tx * 4];
            acc[0][0] += a0 * b4.x; acc[0][1] += a0 * b4.y; acc[0][2] += a0 * b4.z; acc[0][3] += a0 * b4.w;
            acc[1][0] += a1 * b4.x; acc[1][1] += a1 * b4.y; acc[1][2] += a1 * b4.z; acc[1][3] += a1 * b4.w;
            acc[2][0] += a2 * b4.x; acc[2][1] += a2 * b4.y; acc[2][2] += a2 * b4.z; acc[2][3] += a2 * b4.w;
            acc[3][0] += a3 * b4.x; acc[3][1] += a3 * b4.y; acc[3][2] += a3 * b4.z; acc[3][3] += a3 * b4.w;
        }
        __syncthreads();
    }

    int col = col0 + tx * 4;
    float4 bsv = *(const float4*)(bias + col);
    #pragma unroll
    for (int i = 0; i < 4; i++) {
        int r = row0 + ty * 4 + i;
        if (r < M) {
            float4 v;
            v.x = acc[i][0] + bsv.x;
            v.y = acc[i][1] + bsv.y;
            v.z = acc[i][2] + bsv.z;
            v.w = acc[i][3] + bsv.w;
            if (relu) {
                v.x = fmaxf(v.x, 0.f); v.y = fmaxf(v.y, 0.f);
                v.z = fmaxf(v.z, 0.f); v.w = fmaxf(v.w, 0.f);
            }
            *(float4*)(C + (size_t)r * Nc + col) = v;
        }
    }
}

// -------------------- tiled flash attention (fp32) --------------------
// grid: (QT, HH, BB), block 256. 64-query x 64-key tiles, 4x4 register tiles.
__global__ void attn_tile_kernel(const float* __restrict__ Q, const float* __restrict__ Kmat,
                                 const float* __restrict__ V, float* __restrict__ O)
{
    __shared__ float Qs[64][68];   // [d][q]
    __shared__ float Ks[64][68];   // [d][k]
    __shared__ float Vs[64][68];   // [k][d]
    __shared__ float Ps[64][68];   // [q][k]

    int b = blockIdx.z, h = blockIdx.y;
    int q0 = blockIdx.x * 64;
    int tid = threadIdx.x;
    int tx = tid & 15;             // col group
    int ty = tid >> 4;             // row group

    const float* Qb = Q + (size_t)b * SS * 512 + h * 64;
    const float* Kb = Kmat + (size_t)b * SS * 512 + h * 64;
    const float* Vb = V + (size_t)b * SS * 512 + h * 64;

    // Load Q tile transposed: Qs[d][q]
    {
        int r = tid >> 2;
        int dp = (tid & 3) * 4;
        #pragma unroll
        for (int pass = 0; pass < 4; pass++) {
            int d0 = pass * 16 + dp;
            float4 v = make_float4(0.f, 0.f, 0.f, 0.f);
            int q = q0 + r;
            if (q < SS) v = *(const float4*)(Qb + (size_t)q * 512 + d0);
            Qs[d0 + 0][r] = v.x;
            Qs[d0 + 1][r] = v.y;
            Qs[d0 + 2][r] = v.z;
            Qs[d0 + 3][r] = v.w;
        }
    }

    float accO[4][4];
    float m[4], l[4];
    #pragma unroll
    for (int i = 0; i < 4; i++) {
        m[i] = -1e30f; l[i] = 0.f;
        #pragma unroll
        for (int j = 0; j < 4; j++) accO[i][j] = 0.f;
    }

    const float scale = 0.125f;    // 1/sqrt(64)

    for (int k0 = 0; k0 < SS; k0 += 64) {
        // Load K tile transposed (Ks[d][k]) and V tile (Vs[k][d])
        {
            int r = tid >> 2;
            int dp = (tid & 3) * 4;
            #pragma unroll
            for (int pass = 0; pass < 4; pass++) {
                int d0 = pass * 16 + dp;
                float4 kv = make_float4(0.f, 0.f, 0.f, 0.f);
                float4 vv = make_float4(0.f, 0.f, 0.f, 0.f);
                int k = k0 + r;
                if (k < SS) {
                    kv = *(const float4*)(Kb + (size_t)k * 512 + d0);
                    vv = *(const float4*)(Vb + (size_t)k * 512 + d0);
                }
                Ks[d0 + 0][r] = kv.x;
                Ks[d0 + 1][r] = kv.y;
                Ks[d0 + 2][r] = kv.z;
                Ks[d0 + 3][r] = kv.w;
                *(float4*)&Vs[r][d0] = vv;
            }
        }
        __syncthreads();

        // S = Q @ K^T  (thread owns rows 4ty+i, cols 4tx+j)
        float accS[4][4];
        #pragma unroll
        for (int i = 0; i < 4; i++)
            #pragma unroll
            for (int j = 0; j < 4; j++) accS[i][j] = 0.f;

        #pragma unroll 16
        for (int d = 0; d < 64; d++) {
            float4 a4 = *(const float4*)&Qs[d][ty * 4];
            float4 b4 = *(const float4*)&Ks[d][tx * 4];
            accS[0][0] += a4.x * b4.x; accS[0][1] += a4.x * b4.y; accS[0][2] += a4.x * b4.z; accS[0][3] += a4.x * b4.w;
            accS[1][0] += a4.y * b4.x; accS[1][1] += a4.y * b4.y; accS[1][2] += a4.y * b4.z; accS[1][3] += a4.y * b4.w;
            accS[2][0] += a4.z * b4.x; accS[2][1] += a4.z * b4.y; accS[2][2] += a4.z * b4.z; accS[2][3] += a4.z * b4.w;
            accS[3][0] += a4.w * b4.x; accS[3][1] += a4.w * b4.y; accS[3][2] += a4.w * b4.z; accS[3][3] += a4.w * b4.w;
        }

        // online softmax per row (rows live on 16-lane half-warps, same ty)
        #pragma unroll
        for (int i = 0; i < 4; i++) {
            float s0 = (k0 + tx * 4 + 0 < SS) ? accS[i][0] * scale : -1e30f;
            float s1 = (k0 + tx * 4 + 1 < SS) ? accS[i][1] * scale : -1e30f;
            float s2 = (k0 + tx * 4 + 2 < SS) ? accS[i][2] * scale : -1e30f;
            float s3 = (k0 + tx * 4 + 3 < SS) ? accS[i][3] * scale : -1e30f;
            float mloc = fmaxf(fmaxf(s0, s1), fmaxf(s2, s3));
            #pragma unroll
            for (int o = 8; o; o >>= 1) mloc = fmaxf(mloc, __shfl_xor_sync(0xffffffffu, mloc, o));
            float mnew = fmaxf(m[i], mloc);
            float corr = __expf(m[i] - mnew);
            float p0 = __expf(s0 - mnew);
            float p1 = __expf(s1 - mnew);
            float p2 = __expf(s2 - mnew);
            float p3 = __expf(s3 - mnew);
            float rs = p0 + p1 + p2 + p3;
            #pragma unroll
            for (int o = 8; o; o >>= 1) rs += __shfl_xor_sync(0xffffffffu, rs, o);
            l[i] = l[i] * corr + rs;
            m[i] = mnew;
            accO[i][0] *= corr; accO[i][1] *= corr; accO[i][2] *= corr; accO[i][3] *= corr;
            int qr = ty * 4 + i;
            Ps[qr][tx * 4 + 0] = p0;
            Ps[qr][tx * 4 + 1] = p1;
            Ps[qr][tx * 4 + 2] = p2;
            Ps[qr][tx * 4 + 3] = p3;
        }
        __syncthreads();

        // O += P @ V  (thread owns rows 4ty+i of q, cols 4tx+j of d)
        #pragma unroll 8
        for (int kk = 0; kk < 64; kk += 4) {
            float4 pA = *(const float4*)&Ps[ty * 4 + 0][kk];
            float4 pB = *(const float4*)&Ps[ty * 4 + 1][kk];
            float4 pC = *(const float4*)&Ps[ty * 4 + 2][kk];
            float4 pD = *(const float4*)&Ps[ty * 4 + 3][kk];
            #pragma unroll
            for (int t = 0; t < 4; t++) {
                float4 v4 = *(const float4*)&Vs[kk + t][tx * 4];
                float pa = t == 0 ? pA.x : t == 1 ? pA.y : t == 2 ? pA.z : pA.w;
                float pb = t == 0 ? pB.x : t == 1 ? pB.y : t == 2 ? pB.z : pB.w;
                float pc = t == 0 ? pC.x : t == 1 ? pC.y : t == 2 ? pC.z : pC.w;
                float pd = t == 0 ? pD.x : t == 1 ? pD.y : t == 2 ? pD.z : pD.w;
                accO[0][0] += pa * v4.x; accO[0][1] += pa * v4.y; accO[0][2] += pa * v4.z; accO[0][3] += pa * v4.w;
                accO[1][0] += pb * v4.x; accO[1][1] += pb * v4.y; accO[1][2] += pb * v4.z; accO[1][3] += pb * v4.w;
                accO[2][0] += pc * v4.x; accO[2][1] += pc * v4.y; accO[2][2] += pc * v4.z; accO[2][3] += pc * v4.w;
                accO[3][0] += pd * v4.x; accO[3][1] += pd * v4.y; accO[3][2] += pd * v4.z; accO[3][3] += pd * v4.w;
            }
        }
        __syncthreads();
    }

    // store O
    float* Ob = O + (size_t)b * SS * 512 + h * 64;
    #pragma unroll
    for (int i = 0; i < 4; i++) {
        int q = q0 + ty * 4 + i;
        if (q < SS) {
            float inv = 1.f / l[i];
            float4 v;
            v.x = accO[i][0] * inv;
            v.y = accO[i][1] * inv;
            v.z = accO[i][2] * inv;
            v.w = accO[i][3] * inv;
            *(float4*)(Ob + (size_t)q * 512 + tx * 4) = v;
        }
    }
}

// -------------------- x = LayerNorm(x + h) --------------------
__global__ void add_ln_kernel(float* __restrict__ x, const float* __restrict__ h,
                              const float* __restrict__ g, const float* __restrict__ bb)
{
    int row = blockIdx.x, t = threadIdx.x;
    float v = x[(size_t)row * DD + t] + h[(size_t)row * DD + t];
    float s1 = v, s2 = v * v;
    #pragma unroll
    for (int o = 16; o; o >>= 1) {
        s1 += __shfl_xor_sync(0xffffffffu, s1, o);
        s2 += __shfl_xor_sync(0xffffffffu, s2, o);
    }
    __shared__ float r1[8], r2[8];
    int w = t >> 5, ln = t & 31;
    if (ln == 0) { r1[w] = s1; r2[w] = s2; }
    __syncthreads();
    if (w == 0) {
        float a = (ln < 8) ? r1[ln] : 0.f;
        float c = (ln < 8) ? r2[ln] : 0.f;
        #pragma unroll
        for (int o = 4; o; o >>= 1) {
            a += __shfl_xor_sync(0xffffffffu, a, o);
            c += __shfl_xor_sync(0xffffffffu, c, o);
        }
        if (ln == 0) { r1[0] = a; r2[0] = c; }
    }
    __syncthreads();
    float mean = r1[0] * (1.f / 256.f);
    float var = r2[0] * (1.f / 256.f) - mean * mean;
    float rstd = rsqrtf(var + 1e-5f);
    x[(size_t)row * DD + t] = (v - mean) * rstd * g[t] + bb[t];
}

// -------------------- output heads --------------------
// node logits: grid BB*NN blocks, 256 threads
__global__ void node_out_kernel(const float* __restrict__ x, const float* __restrict__ w,
                                const float* __restrict__ bias, float* __restrict__ out)
{
    int idx = blockIdx.x;            // b*NN + i
    int b = idx / NN, i = idx % NN;
    int t = threadIdx.x;
    __shared__ float xr[DD];
    xr[t] = x[(size_t)(b * SS + i) * DD + t];
    __syncthreads();
    int wrp = t >> 5, ln = t & 31;
    #pragma unroll
    for (int cb = 0; cb < 24; cb += 8) {
        int c = cb + wrp;
        float s = 0.f;
        if (c < NFD) {
            #pragma unroll
            for (int k = 0; k < 8; k++) s += xr[ln + 32 * k] * w[(ln + 32 * k) * NFD + c];
        }
        #pragma unroll
        for (int o = 16; o; o >>= 1) s += __shfl_xor_sync(0xffffffffu, s, o);
        if (ln == 0 && c < NFD) out[(size_t)idx * NFD + c] = s + bias[c];
    }
}

// edge logits (symmetrized): grid BB*NN*NN, 256 threads
__global__ void edge_out_kernel(const float* __restrict__ x, const float* __restrict__ w,
                                const float* __restrict__ bias, float* __restrict__ out)
{
    int idx = blockIdx.x;            // b*NN*NN + i*NN + j
    int b = idx / (NN * NN);
    int r = idx % (NN * NN);
    int i = r / NN, j = r % NN;
    int t = threadIdx.x;
    __shared__ float sr[DD];
    const float* xi = x + (size_t)(b * SS + NN + i * NN + j) * DD;
    const float* xj = x + (size_t)(b * SS + NN + j * NN + i) * DD;
    sr[t] = xi[t] + xj[t];
    __syncthreads();
    int wrp = t >> 5, ln = t & 31;
    int c = wrp;
    float s = 0.f;
    if (c < NED) {
        #pragma unroll
        for (int k = 0; k < 8; k++) s += sr[ln + 32 * k] * w[(ln + 32 * k) * NED + c];
    }
    #pragma unroll
    for (int o = 16; o; o >>= 1) s += __shfl_xor_sync(0xffffffffu, s, o);
    if (ln == 0 && c < NED) out[(size_t)idx * NED + c] = 0.5f * s + bias[c];
}

// -------------------- host orchestration --------------------
static inline float* sym_addr(const void* sym)
{
    void* p = nullptr;
    cudaGetSymbolAddress(&p, sym);
    return (float*)p;
}

extern "C" void kernel_launch(void* const* d_in, const int* in_sizes, int n_in,
                              void* d_out, int out_size)
{
    (void)in_sizes; (void)n_in; (void)out_size;
    const float* graph_emb = (const float*)d_in[0];
    const float* perm      = (const float*)d_in[1];
    // d_in[2] = mask (all true) — masking is a no-op
    const float* pnw = (const float*)d_in[3];
    const float* pnb = (const float*)d_in[4];
    const float* pew = (const float*)d_in[5];
    const float* peb = (const float*)d_in[6];
    const float* now_ = (const float*)d_in[7];
    const float* nob = (const float*)d_in[8];
    const float* eow = (const float*)d_in[9];
    const float* eob = (const float*)d_in[10];
    const float* Wq = (const float*)d_in[11];
    const float* bq = (const float*)d_in[12];
    const float* Wk = (const float*)d_in[13];
    const float* bk = (const float*)d_in[14];
    const float* Wv = (const float*)d_in[15];
    const float* bv = (const float*)d_in[16];
    const float* Wo = (const float*)d_in[17];
    const float* bo = (const float*)d_in[18];
    const float* W1 = (const float*)d_in[19];
    const float* b1 = (const float*)d_in[20];
    const float* W2 = (const float*)d_in[21];
    const float* b2 = (const float*)d_in[22];
    const float* ln1g = (const float*)d_in[23];
    const float* ln1b = (const float*)d_in[24];
    const float* ln2g = (const float*)d_in[25];
    const float* ln2b = (const float*)d_in[26];

    float* px   = sym_addr(g_x);
    float* ppos = sym_addr(g_pos);
    float* pq   = sym_addr(g_q);
    float* pk   = sym_addr(g_k);
    float* pv   = sym_addr(g_v);
    float* pat  = sym_addr(g_attn);
    float* pt   = sym_addr(g_t);
    float* pff  = sym_addr(g_ff);

    const int MROWS = BS;                 // 4704
    const int MTILES = (MROWS + 63) / 64; // 74

    pos_kernel<<<BB * NN, 32>>>(perm, ppos);
    embed_kernel<<<BS, 256>>>(graph_emb, ppos, pnw, pnb, pew, peb, px);

    for (int l = 0; l < LL; l++) {
        const float* wq = Wq + (size_t)l * DD * 512;
        const float* wk = Wk + (size_t)l * DD * 512;
        const float* wv = Wv + (size_t)l * DD * 512;
        const float* wo = Wo + (size_t)l * 512 * DD;
        const float* w1 = W1 + (size_t)l * DD * FFD;
        const float* w2 = W2 + (size_t)l * FFD * DD;

        gemm_bias_kernel<<<dim3(512 / 64, MTILES), 256>>>(px, wq, bq + l * 512, pq, MROWS, DD, 512, 0);
        gemm_bias_kernel<<<dim3(512 / 64, MTILES), 256>>>(px, wk, bk + l * 512, pk, MROWS, DD, 512, 0);
        gemm_bias_kernel<<<dim3(512 / 64, MTILES), 256>>>(px, wv, bv + l * 512, pv, MROWS, DD, 512, 0);

        attn_tile_kernel<<<dim3(QT, HH, BB), 256>>>(pq, pk, pv, pat);

        gemm_bias_kernel<<<dim3(DD / 64, MTILES), 256>>>(pat, wo, bo + l * DD, pt, MROWS, 512, DD, 0);
        add_ln_kernel<<<BS, 256>>>(px, pt, ln1g + l * DD, ln1b + l * DD);

        gemm_bias_kernel<<<dim3(FFD / 64, MTILES), 256>>>(px, w1, b1 + l * FFD, pff, MROWS, DD, FFD, 1);
        gemm_bias_kernel<<<dim3(DD / 64, MTILES), 256>>>(pff, w2, b2 + l * DD, pt, MROWS, FFD, DD, 0);
        add_ln_kernel<<<BS, 256>>>(px, pt, ln2g + l * DD, ln2b + l * DD);
    }

    float* out = (float*)d_out;
    node_out_kernel<<<BB * NN, 256>>>(px, now_, nob, out);
    edge_out_kernel<<<BB * NN * NN, 256>>>(px, eow, eob, out + BB * NN * NFD);
}

// round 3
// speedup vs baseline: 11.9731x; 1.8590x over previous
#include <cuda_runtime.h>
#include <cuda_bf16.h>
#include <math.h>
#include <stdint.h>

// Problem constants
#define BB 2
#define NN 48
#define DD 256
#define HH 8
#define DKV 64
#define FFD 1024
#define LL 4
#define PDD 32
#define NFD 20
#define NED 5
#define SS 2352           // NN + NN*NN
#define BS 4704           // BB*SS
#define QT 37             // ceil(SS/64) query tiles

// -------------------- scratch (device globals; no allocation) --------------------
__device__ float g_pos[BB * NN * PDD];
__device__ float g_x[BS * DD];
__device__ float g_q[BS * HH * DKV];
__device__ float g_k[BS * HH * DKV];
__device__ float g_v[BS * HH * DKV];
__device__ float g_attn[BS * HH * DKV];
__device__ float g_t[BS * DD];
__device__ float g_ff[BS * FFD];

// -------------------- helpers --------------------
__device__ __forceinline__ float to_tf32(float x)
{
    uint32_t u;
    asm("cvt.rna.tf32.f32 %0, %1;" : "=r"(u) : "f"(x));
    return __uint_as_float(u);
}

__device__ __forceinline__ void mma_tf32(float* d, const uint32_t* a, const uint32_t* b)
{
    asm volatile(
        "mma.sync.aligned.m16n8k8.row.col.f32.tf32.tf32.f32 "
        "{%0,%1,%2,%3}, {%4,%5,%6,%7}, {%8,%9}, {%0,%1,%2,%3};"
        : "+f"(d[0]), "+f"(d[1]), "+f"(d[2]), "+f"(d[3])
        : "r"(a[0]), "r"(a[1]), "r"(a[2]), "r"(a[3]), "r"(b[0]), "r"(b[1]));
}

// -------------------- pos = perm @ posenc --------------------
__global__ void pos_kernel(const float* __restrict__ perm, float* __restrict__ pos)
{
    int row = blockIdx.x;            // b*NN + i
    int d = threadIdx.x;             // 0..31
    const float* pr = perm + (size_t)row * NN;
    float freq = expf(-logf(10000.f) * (float)(d & ~1) / (float)PDD);
    float s = 0.f;
    #pragma unroll 8
    for (int j = 0; j < NN; j++) {
        float ang = (float)j * freq;
        float pe = (d & 1) ? cosf(ang) : sinf(ang);
        s += pr[j] * pe;
    }
    pos[row * PDD + d] = s;
}

// -------------------- token embedding --------------------
__global__ void embed_kernel(const float* __restrict__ ge, const float* __restrict__ pos,
                             const float* __restrict__ pnw, const float* __restrict__ pnb,
                             const float* __restrict__ pew, const float* __restrict__ peb,
                             float* __restrict__ x)
{
    int tok = blockIdx.x;
    int b = tok / SS;
    int r = tok % SS;
    int d = threadIdx.x;
    __shared__ float pi[PDD];
    __shared__ float pj[PDD];

    if (r < NN) {
        if (d < PDD) pi[d] = pos[(b * NN + r) * PDD + d];
        __syncthreads();
        float s = ge[b * DD + d] + pnb[d];
        #pragma unroll
        for (int p = 0; p < PDD; p++) s += pi[p] * pnw[p * DD + d];
        x[(size_t)tok * DD + d] = s;
    } else {
        int e = r - NN;
        int i = e / NN, j = e % NN;
        if (d < PDD) pi[d] = pos[(b * NN + i) * PDD + d];
        else if (d < 2 * PDD) pj[d - PDD] = pos[(b * NN + j) * PDD + (d - PDD)];
        __syncthreads();
        float s = ge[b * DD + d] + peb[d];
        #pragma unroll
        for (int p = 0; p < PDD; p++) s += pi[p] * pew[p * DD + d];
        #pragma unroll
        for (int p = 0; p < PDD; p++) s += pj[p] * pew[(PDD + p) * DD + d];
        x[(size_t)tok * DD + d] = s;
    }
}

// -------------------- tf32 tensor-core GEMM: C = act(A @ W + bias) --------------------
// A: MxK fp32 row-major, W: KxN fp32 row-major. K%32==0, N%64==0, M bounds-checked.
// Block: 256 threads (8 warps), tile 128(M) x 64(N), BK=32.
// Warp layout 4x2 -> each warp 32x32, frags 2(m16) x 4(n8), tf32 m16n8k8.
__global__ __launch_bounds__(256) void gemm_tf32_kernel(
    const float* __restrict__ A, const float* __restrict__ W,
    const float* __restrict__ bias, float* __restrict__ C,
    int M, int K, int N, int relu)
{
    __shared__ float As[128][36];
    __shared__ float Bs[32][72];

    int tid = threadIdx.x;
    int warp = tid >> 5, lane = tid & 31;
    int g = lane >> 2, t = lane & 3;
    int wm = warp >> 1, wn = warp & 1;
    int m0 = wm * 32;
    int n0w = wn * 32;
    int brow0 = blockIdx.y * 128;
    int bcol0 = blockIdx.x * 64;

    float acc[2][4][4];
    #pragma unroll
    for (int mi = 0; mi < 2; mi++)
        #pragma unroll
        for (int ni = 0; ni < 4; ni++)
            #pragma unroll
            for (int v = 0; v < 4; v++) acc[mi][ni][v] = 0.f;

    int ar = tid >> 1;                 // 0..127
    int acb = (tid & 1) * 16;          // 0 or 16

    for (int k0 = 0; k0 < K; k0 += 32) {
        // load A tile 128x32
        {
            int grow = brow0 + ar;
            #pragma unroll
            for (int i = 0; i < 4; i++) {
                int c = acb + i * 4;
                float4 v = make_float4(0.f, 0.f, 0.f, 0.f);
                if (grow < M) v = *(const float4*)(A + (size_t)grow * K + k0 + c);
                float4 w;
                w.x = to_tf32(v.x); w.y = to_tf32(v.y);
                w.z = to_tf32(v.z); w.w = to_tf32(v.w);
                *(float4*)&As[ar][c] = w;
            }
        }
        // load B tile 32x64
        {
            #pragma unroll
            for (int i = 0; i < 2; i++) {
                int lin4 = tid * 2 + i;            // 0..511
                int brow = lin4 >> 4;              // 0..31
                int c = (lin4 & 15) * 4;           // 0..60
                float4 v = *(const float4*)(W + (size_t)(k0 + brow) * N + bcol0 + c);
                float4 w;
                w.x = to_tf32(v.x); w.y = to_tf32(v.y);
                w.z = to_tf32(v.z); w.w = to_tf32(v.w);
                *(float4*)&Bs[brow][c] = w;
            }
        }
        __syncthreads();

        #pragma unroll
        for (int k8 = 0; k8 < 4; k8++) {
            int kk = k8 * 8;
            uint32_t afr[2][4];
            #pragma unroll
            for (int mi = 0; mi < 2; mi++) {
                int row = m0 + mi * 16;
                afr[mi][0] = __float_as_uint(As[row + g][kk + t]);
                afr[mi][1] = __float_as_uint(As[row + g + 8][kk + t]);
                afr[mi][2] = __float_as_uint(As[row + g][kk + t + 4]);
                afr[mi][3] = __float_as_uint(As[row + g + 8][kk + t + 4]);
            }
            uint32_t bfr[4][2];
            #pragma unroll
            for (int ni = 0; ni < 4; ni++) {
                int col = n0w + ni * 8;
                bfr[ni][0] = __float_as_uint(Bs[kk + t][col + g]);
                bfr[ni][1] = __float_as_uint(Bs[kk + t + 4][col + g]);
            }
            #pragma unroll
            for (int mi = 0; mi < 2; mi++)
                #pragma unroll
                for (int ni = 0; ni < 4; ni++)
                    mma_tf32(acc[mi][ni], afr[mi], bfr[ni]);
        }
        __syncthreads();
    }

    // epilogue: bias (+relu), fp32 store
    #pragma unroll
    for (int ni = 0; ni < 4; ni++) {
        int col = bcol0 + n0w + ni * 8 + 2 * t;
        float b0 = bias[col], b1 = bias[col + 1];
        #pragma unroll
        for (int mi = 0; mi < 2; mi++) {
            int row = brow0 + m0 + mi * 16 + g;
            float v0 = acc[mi][ni][0] + b0;
            float v1 = acc[mi][ni][1] + b1;
            float v2 = acc[mi][ni][2] + b0;
            float v3 = acc[mi][ni][3] + b1;
            if (relu) {
                v0 = fmaxf(v0, 0.f); v1 = fmaxf(v1, 0.f);
                v2 = fmaxf(v2, 0.f); v3 = fmaxf(v3, 0.f);
            }
            if (row < M)     { float2 p = make_float2(v0, v1); *(float2*)(C + (size_t)row * N + col) = p; }
            if (row + 8 < M) { float2 p = make_float2(v2, v3); *(float2*)(C + (size_t)(row + 8) * N + col) = p; }
        }
    }
}

// -------------------- tf32 tensor-core flash attention --------------------
// grid: (QT, HH, BB), block 256 (8 warps). 64-query x 64-key tiles.
// S phase: warps 2(m) x 4(n) -> warp 32x16 of S;  PV: same layout over (q x d).
#define ATT_SM_FLOATS (64 * (68 + 68 + 72 + 68) + 64 * 3)
#define ATT_SM_BYTES (ATT_SM_FLOATS * 4)

__global__ __launch_bounds__(256) void attn_mma_kernel(
    const float* __restrict__ Q, const float* __restrict__ Kmat,
    const float* __restrict__ V, float* __restrict__ O)
{
    extern __shared__ float sm[];
    float (*Qs)[68] = (float(*)[68])sm;
    float (*Ks)[68] = (float(*)[68])(sm + 64 * 68);
    float (*Vs)[72] = (float(*)[72])(sm + 64 * 68 * 2);
    float (*Sx)[68] = (float(*)[68])(sm + 64 * 68 * 2 + 64 * 72);
    float* m_s   = sm + 64 * 68 * 3 + 64 * 72;
    float* l_s   = m_s + 64;
    float* cr_s  = m_s + 128;

    int b = blockIdx.z, h = blockIdx.y;
    int q0 = blockIdx.x * 64;
    int tid = threadIdx.x;
    int warp = tid >> 5, lane = tid & 31;
    int g = lane >> 2, t = lane & 3;
    int wm = warp >> 2;          // 0..1
    int wn = warp & 3;           // 0..3
    int m0 = wm * 32;

    const float* Qb = Q + (size_t)b * SS * 512 + h * 64;
    const float* Kb = Kmat + (size_t)b * SS * 512 + h * 64;
    const float* Vb = V + (size_t)b * SS * 512 + h * 64;

    int lr = tid >> 2;               // 0..63 row for tile loads
    int lcb = (tid & 3) * 16;        // col base

    // load Q tile (tf32) and init softmax state
    #pragma unroll
    for (int i = 0; i < 4; i++) {
        int c = lcb + i * 4;
        float4 v = make_float4(0.f, 0.f, 0.f, 0.f);
        if (q0 + lr < SS) v = *(const float4*)(Qb + (size_t)(q0 + lr) * 512 + c);
        float4 w;
        w.x = to_tf32(v.x); w.y = to_tf32(v.y);
        w.z = to_tf32(v.z); w.w = to_tf32(v.w);
        *(float4*)&Qs[lr][c] = w;
    }
    if (tid < 64) { m_s[tid] = -1e30f; l_s[tid] = 0.f; }

    float accO[2][2][4];
    #pragma unroll
    for (int mi = 0; mi < 2; mi++)
        #pragma unroll
        for (int ni = 0; ni < 2; ni++)
            #pragma unroll
            for (int v = 0; v < 4; v++) accO[mi][ni][v] = 0.f;

    const float scale = 0.125f;      // 1/sqrt(64)

    for (int kt0 = 0; kt0 < SS; kt0 += 64) {
        // load K and V tiles (tf32, zero-padded)
        #pragma unroll
        for (int i = 0; i < 4; i++) {
            int c = lcb + i * 4;
            float4 kv = make_float4(0.f, 0.f, 0.f, 0.f);
            float4 vv = make_float4(0.f, 0.f, 0.f, 0.f);
            if (kt0 + lr < SS) {
                kv = *(const float4*)(Kb + (size_t)(kt0 + lr) * 512 + c);
                vv = *(const float4*)(Vb + (size_t)(kt0 + lr) * 512 + c);
            }
            float4 kw, vw;
            kw.x = to_tf32(kv.x); kw.y = to_tf32(kv.y); kw.z = to_tf32(kv.z); kw.w = to_tf32(kv.w);
            vw.x = to_tf32(vv.x); vw.y = to_tf32(vv.y); vw.z = to_tf32(vv.z); vw.w = to_tf32(vv.w);
            *(float4*)&Ks[lr][c] = kw;
            *(float4*)&Vs[lr][c] = vw;
        }
        __syncthreads();

        // ---- S = Q @ K^T (tf32 mma) ----
        float accS[2][2][4];
        #pragma unroll
        for (int mi = 0; mi < 2; mi++)
            #pragma unroll
            for (int ni = 0; ni < 2; ni++)
                #pragma unroll
                for (int v = 0; v < 4; v++) accS[mi][ni][v] = 0.f;

        #pragma unroll
        for (int k8 = 0; k8 < 8; k8++) {
            int kk = k8 * 8;
            uint32_t afr[2][4];
            #pragma unroll
            for (int mi = 0; mi < 2; mi++) {
                int row = m0 + mi * 16;
                afr[mi][0] = __float_as_uint(Qs[row + g][kk + t]);
                afr[mi][1] = __float_as_uint(Qs[row + g + 8][kk + t]);
                afr[mi][2] = __float_as_uint(Qs[row + g][kk + t + 4]);
                afr[mi][3] = __float_as_uint(Qs[row + g + 8][kk + t + 4]);
            }
            uint32_t bfr[2][2];
            #pragma unroll
            for (int ni = 0; ni < 2; ni++) {
                int col = wn * 16 + ni * 8;
                bfr[ni][0] = __float_as_uint(Ks[col + g][kk + t]);
                bfr[ni][1] = __float_as_uint(Ks[col + g][kk + t + 4]);
            }
            #pragma unroll
            for (int mi = 0; mi < 2; mi++)
                #pragma unroll
                for (int ni = 0; ni < 2; ni++)
                    mma_tf32(accS[mi][ni], afr[mi], bfr[ni]);
        }

        // store scaled S to smem
        #pragma unroll
        for (int mi = 0; mi < 2; mi++) {
            int row = m0 + mi * 16 + g;
            #pragma unroll
            for (int ni = 0; ni < 2; ni++) {
                int col = wn * 16 + ni * 8 + 2 * t;
                float2 p0 = make_float2(accS[mi][ni][0] * scale, accS[mi][ni][1] * scale);
                float2 p1 = make_float2(accS[mi][ni][2] * scale, accS[mi][ni][3] * scale);
                *(float2*)&Sx[row][col] = p0;
                *(float2*)&Sx[row + 8][col] = p1;
            }
        }
        __syncthreads();

        // ---- online softmax on Sx (4 threads per row, 16 cols each) ----
        {
            int row = tid >> 2;
            int tc = tid & 3;
            float* srow = Sx[row];
            float vals[16];
            float lm = -1e30f;
            #pragma unroll
            for (int i = 0; i < 4; i++) {
                float4 v = *(const float4*)&srow[tc * 16 + i * 4];
                vals[i * 4 + 0] = v.x; vals[i * 4 + 1] = v.y;
                vals[i * 4 + 2] = v.z; vals[i * 4 + 3] = v.w;
            }
            #pragma unroll
            for (int c = 0; c < 16; c++) {
                int kg = kt0 + tc * 16 + c;
                if (kg >= SS) vals[c] = -1e30f;
                lm = fmaxf(lm, vals[c]);
            }
            lm = fmaxf(lm, __shfl_xor_sync(0xffffffffu, lm, 1));
            lm = fmaxf(lm, __shfl_xor_sync(0xffffffffu, lm, 2));
            float mold = m_s[row];
            float mnew = fmaxf(mold, lm);
            float corr = __expf(mold - mnew);
            float ps = 0.f;
            #pragma unroll
            for (int c = 0; c < 16; c++) {
                float p = __expf(vals[c] - mnew);
                ps += p;
                vals[c] = to_tf32(p);
            }
            ps += __shfl_xor_sync(0xffffffffu, ps, 1);
            ps += __shfl_xor_sync(0xffffffffu, ps, 2);
            #pragma unroll
            for (int i = 0; i < 4; i++) {
                float4 v = make_float4(vals[i * 4 + 0], vals[i * 4 + 1], vals[i * 4 + 2], vals[i * 4 + 3]);
                *(float4*)&srow[tc * 16 + i * 4] = v;
            }
            if (tc == 0) {
                m_s[row] = mnew;
                l_s[row] = l_s[row] * corr + ps;
                cr_s[row] = corr;
            }
        }
        __syncthreads();

        // rescale accO by corr
        #pragma unroll
        for (int mi = 0; mi < 2; mi++) {
            float c0 = cr_s[m0 + mi * 16 + g];
            float c1 = cr_s[m0 + mi * 16 + g + 8];
            #pragma unroll
            for (int ni = 0; ni < 2; ni++) {
                accO[mi][ni][0] *= c0; accO[mi][ni][1] *= c0;
                accO[mi][ni][2] *= c1; accO[mi][ni][3] *= c1;
            }
        }

        // ---- O += P @ V (tf32 mma) ----
        #pragma unroll
        for (int k8 = 0; k8 < 8; k8++) {
            int kk = k8 * 8;
            uint32_t afr[2][4];
            #pragma unroll
            for (int mi = 0; mi < 2; mi++) {
                int row = m0 + mi * 16;
                afr[mi][0] = __float_as_uint(Sx[row + g][kk + t]);
                afr[mi][1] = __float_as_uint(Sx[row + g + 8][kk + t]);
                afr[mi][2] = __float_as_uint(Sx[row + g][kk + t + 4]);
                afr[mi][3] = __float_as_uint(Sx[row + g + 8][kk + t + 4]);
            }
            uint32_t bfr[2][2];
            #pragma unroll
            for (int ni = 0; ni < 2; ni++) {
                int col = wn * 16 + ni * 8;
                bfr[ni][0] = __float_as_uint(Vs[kk + t][col + g]);
                bfr[ni][1] = __float_as_uint(Vs[kk + t + 4][col + g]);
            }
            #pragma unroll
            for (int mi = 0; mi < 2; mi++)
                #pragma unroll
                for (int ni = 0; ni < 2; ni++)
                    mma_tf32(accO[mi][ni], afr[mi], bfr[ni]);
        }
        __syncthreads();
    }

    // final store: O / l
    float* Ob = O + (size_t)b * SS * 512 + h * 64;
    #pragma unroll
    for (int mi = 0; mi < 2; mi++) {
        int r1 = m0 + mi * 16 + g;
        int r2 = r1 + 8;
        float inv1 = 1.f / l_s[r1];
        float inv2 = 1.f / l_s[r2];
        #pragma unroll
        for (int ni = 0; ni < 2; ni++) {
            int col = wn * 16 + ni * 8 + 2 * t;
            if (q0 + r1 < SS) {
                float2 p = make_float2(accO[mi][ni][0] * inv1, accO[mi][ni][1] * inv1);
                *(float2*)(Ob + (size_t)(q0 + r1) * 512 + col) = p;
            }
            if (q0 + r2 < SS) {
                float2 p = make_float2(accO[mi][ni][2] * inv2, accO[mi][ni][3] * inv2);
                *(float2*)(Ob + (size_t)(q0 + r2) * 512 + col) = p;
            }
        }
    }
}

// -------------------- x = LayerNorm(x + h) --------------------
__global__ void add_ln_kernel(float* __restrict__ x, const float* __restrict__ h,
                              const float* __restrict__ g, const float* __restrict__ bb)
{
    int row = blockIdx.x, t = threadIdx.x;
    float v = x[(size_t)row * DD + t] + h[(size_t)row * DD + t];
    float s1 = v, s2 = v * v;
    #pragma unroll
    for (int o = 16; o; o >>= 1) {
        s1 += __shfl_xor_sync(0xffffffffu, s1, o);
        s2 += __shfl_xor_sync(0xffffffffu, s2, o);
    }
    __shared__ float r1[8], r2[8];
    int w = t >> 5, ln = t & 31;
    if (ln == 0) { r1[w] = s1; r2[w] = s2; }
    __syncthreads();
    if (w == 0) {
        float a = (ln < 8) ? r1[ln] : 0.f;
        float c = (ln < 8) ? r2[ln] : 0.f;
        #pragma unroll
        for (int o = 4; o; o >>= 1) {
            a += __shfl_xor_sync(0xffffffffu, a, o);
            c += __shfl_xor_sync(0xffffffffu, c, o);
        }
        if (ln == 0) { r1[0] = a; r2[0] = c; }
    }
    __syncthreads();
    float mean = r1[0] * (1.f / 256.f);
    float var = r2[0] * (1.f / 256.f) - mean * mean;
    float rstd = rsqrtf(var + 1e-5f);
    x[(size_t)row * DD + t] = (v - mean) * rstd * g[t] + bb[t];
}

// -------------------- output heads --------------------
__global__ void node_out_kernel(const float* __restrict__ x, const float* __restrict__ w,
                                const float* __restrict__ bias, float* __restrict__ out)
{
    int idx = blockIdx.x;            // b*NN + i
    int b = idx / NN, i = idx % NN;
    int t = threadIdx.x;
    __shared__ float xr[DD];
    xr[t] = x[(size_t)(b * SS + i) * DD + t];
    __syncthreads();
    int wrp = t >> 5, ln = t & 31;
    #pragma unroll
    for (int cb = 0; cb < 24; cb += 8) {
        int c = cb + wrp;
        float s = 0.f;
        if (c < NFD) {
            #pragma unroll
            for (int k = 0; k < 8; k++) s += xr[ln + 32 * k] * w[(ln + 32 * k) * NFD + c];
        }
        #pragma unroll
        for (int o = 16; o; o >>= 1) s += __shfl_xor_sync(0xffffffffu, s, o);
        if (ln == 0 && c < NFD) out[(size_t)idx * NFD + c] = s + bias[c];
    }
}

__global__ void edge_out_kernel(const float* __restrict__ x, const float* __restrict__ w,
                                const float* __restrict__ bias, float* __restrict__ out)
{
    int idx = blockIdx.x;            // b*NN*NN + i*NN + j
    int b = idx / (NN * NN);
    int r = idx % (NN * NN);
    int i = r / NN, j = r % NN;
    int t = threadIdx.x;
    __shared__ float sr[DD];
    const float* xi = x + (size_t)(b * SS + NN + i * NN + j) * DD;
    const float* xj = x + (size_t)(b * SS + NN + j * NN + i) * DD;
    sr[t] = xi[t] + xj[t];
    __syncthreads();
    int wrp = t >> 5, ln = t & 31;
    int c = wrp;
    float s = 0.f;
    if (c < NED) {
        #pragma unroll
        for (int k = 0; k < 8; k++) s += sr[ln + 32 * k] * w[(ln + 32 * k) * NED + c];
    }
    #pragma unroll
    for (int o = 16; o; o >>= 1) s += __shfl_xor_sync(0xffffffffu, s, o);
    if (ln == 0 && c < NED) out[(size_t)idx * NED + c] = 0.5f * s + bias[c];
}

// -------------------- host orchestration --------------------
static inline float* sym_addr(const void* sym)
{
    void* p = nullptr;
    cudaGetSymbolAddress(&p, sym);
    return (float*)p;
}

extern "C" void kernel_launch(void* const* d_in, const int* in_sizes, int n_in,
                              void* d_out, int out_size)
{
    (void)in_sizes; (void)n_in; (void)out_size;
    const float* graph_emb = (const float*)d_in[0];
    const float* perm      = (const float*)d_in[1];
    // d_in[2] = mask (all true) — masking is a no-op
    const float* pnw = (const float*)d_in[3];
    const float* pnb = (const float*)d_in[4];
    const float* pew = (const float*)d_in[5];
    const float* peb = (const float*)d_in[6];
    const float* now_ = (const float*)d_in[7];
    const float* nob = (const float*)d_in[8];
    const float* eow = (const float*)d_in[9];
    const float* eob = (const float*)d_in[10];
    const float* Wq = (const float*)d_in[11];
    const float* bq = (const float*)d_in[12];
    const float* Wk = (const float*)d_in[13];
    const float* bk = (const float*)d_in[14];
    const float* Wv = (const float*)d_in[15];
    const float* bv = (const float*)d_in[16];
    const float* Wo = (const float*)d_in[17];
    const float* bo = (const float*)d_in[18];
    const float* W1 = (const float*)d_in[19];
    const float* b1 = (const float*)d_in[20];
    const float* W2 = (const float*)d_in[21];
    const float* b2 = (const float*)d_in[22];
    const float* ln1g = (const float*)d_in[23];
    const float* ln1b = (const float*)d_in[24];
    const float* ln2g = (const float*)d_in[25];
    const float* ln2b = (const float*)d_in[26];

    float* px   = sym_addr(g_x);
    float* ppos = sym_addr(g_pos);
    float* pq   = sym_addr(g_q);
    float* pk   = sym_addr(g_k);
    float* pv   = sym_addr(g_v);
    float* pat  = sym_addr(g_attn);
    float* pt   = sym_addr(g_t);
    float* pff  = sym_addr(g_ff);

    cudaFuncSetAttribute(attn_mma_kernel, cudaFuncAttributeMaxDynamicSharedMemorySize, ATT_SM_BYTES);

    const int MROWS = BS;                   // 4704
    const int MT128 = (MROWS + 127) / 128;  // 37

    pos_kernel<<<BB * NN, 32>>>(perm, ppos);
    embed_kernel<<<BS, 256>>>(graph_emb, ppos, pnw, pnb, pew, peb, px);

    for (int l = 0; l < LL; l++) {
        const float* wq = Wq + (size_t)l * DD * 512;
        const float* wk = Wk + (size_t)l * DD * 512;
        const float* wv = Wv + (size_t)l * DD * 512;
        const float* wo = Wo + (size_t)l * 512 * DD;
        const float* w1 = W1 + (size_t)l * DD * FFD;
        const float* w2 = W2 + (size_t)l * FFD * DD;

        gemm_tf32_kernel<<<dim3(512 / 64, MT128), 256>>>(px, wq, bq + l * 512, pq, MROWS, DD, 512, 0);
        gemm_tf32_kernel<<<dim3(512 / 64, MT128), 256>>>(px, wk, bk + l * 512, pk, MROWS, DD, 512, 0);
        gemm_tf32_kernel<<<dim3(512 / 64, MT128), 256>>>(px, wv, bv + l * 512, pv, MROWS, DD, 512, 0);

        attn_mma_kernel<<<dim3(QT, HH, BB), 256, ATT_SM_BYTES>>>(pq, pk, pv, pat);

        gemm_tf32_kernel<<<dim3(DD / 64, MT128), 256>>>(pat, wo, bo + l * DD, pt, MROWS, 512, DD, 0);
        add_ln_kernel<<<BS, 256>>>(px, pt, ln1g + l * DD, ln1b + l * DD);

        gemm_tf32_kernel<<<dim3(FFD / 64, MT128), 256>>>(px, w1, b1 + l * FFD, pff, MROWS, DD, FFD, 1);
        gemm_tf32_kernel<<<dim3(DD / 64, MT128), 256>>>(pff, w2, b2 + l * DD, pt, MROWS, FFD, DD, 0);
        add_ln_kernel<<<BS, 256>>>(px, pt, ln2g + l * DD, ln2b + l * DD);
    }

    float* out = (float*)d_out;
    node_out_kernel<<<BB * NN, 256>>>(px, now_, nob, out);
    edge_out_kernel<<<BB * NN * NN, 256>>>(px, eow, eob, out + BB * NN * NFD);
}

// round 4
// speedup vs baseline: 15.3995x; 1.2862x over previous
#include <cuda_runtime.h>
#include <cuda_bf16.h>
#include <math.h>
#include <stdint.h>

// Problem constants
#define BB 2
#define NN 48
#define DD 256
#define HH 8
#define DKV 64
#define FFD 1024
#define LL 4
#define PDD 32
#define NFD 20
#define NED 5
#define SS 2352           // NN + NN*NN
#define BS 4704           // BB*SS
#define BQ 128
#define QT2 ((SS + BQ - 1) / BQ)   // 19

// -------------------- scratch (device globals; no allocation) --------------------
__device__ float g_pos[BB * NN * PDD];
__device__ float g_x[BS * DD];
__device__ float g_q[BS * HH * DKV];
__device__ float g_k[BS * HH * DKV];
__device__ float g_v[BS * HH * DKV];
__device__ float g_attn[BS * HH * DKV];
__device__ float g_t[BS * DD];
__device__ float g_ff[BS * FFD];

// -------------------- helpers --------------------
__device__ __forceinline__ float to_tf32(float x)
{
    uint32_t u;
    asm("cvt.rna.tf32.f32 %0, %1;" : "=r"(u) : "f"(x));
    return __uint_as_float(u);
}

__device__ __forceinline__ void mma_tf32(float* d, const uint32_t* a, const uint32_t* b)
{
    asm volatile(
        "mma.sync.aligned.m16n8k8.row.col.f32.tf32.tf32.f32 "
        "{%0,%1,%2,%3}, {%4,%5,%6,%7}, {%8,%9}, {%0,%1,%2,%3};"
        : "+f"(d[0]), "+f"(d[1]), "+f"(d[2]), "+f"(d[3])
        : "r"(a[0]), "r"(a[1]), "r"(a[2]), "r"(a[3]), "r"(b[0]), "r"(b[1]));
}

// -------------------- pos = perm @ posenc --------------------
__global__ void pos_kernel(const float* __restrict__ perm, float* __restrict__ pos)
{
    int row = blockIdx.x;
    int d = threadIdx.x;
    const float* pr = perm + (size_t)row * NN;
    float freq = expf(-logf(10000.f) * (float)(d & ~1) / (float)PDD);
    float s = 0.f;
    #pragma unroll 8
    for (int j = 0; j < NN; j++) {
        float ang = (float)j * freq;
        float pe = (d & 1) ? cosf(ang) : sinf(ang);
        s += pr[j] * pe;
    }
    pos[row * PDD + d] = s;
}

// -------------------- token embedding --------------------
__global__ void embed_kernel(const float* __restrict__ ge, const float* __restrict__ pos,
                             const float* __restrict__ pnw, const float* __restrict__ pnb,
                             const float* __restrict__ pew, const float* __restrict__ peb,
                             float* __restrict__ x)
{
    int tok = blockIdx.x;
    int b = tok / SS;
    int r = tok % SS;
    int d = threadIdx.x;
    __shared__ float pi[PDD];
    __shared__ float pj[PDD];

    if (r < NN) {
        if (d < PDD) pi[d] = pos[(b * NN + r) * PDD + d];
        __syncthreads();
        float s = ge[b * DD + d] + pnb[d];
        #pragma unroll
        for (int p = 0; p < PDD; p++) s += pi[p] * pnw[p * DD + d];
        x[(size_t)tok * DD + d] = s;
    } else {
        int e = r - NN;
        int i = e / NN, j = e % NN;
        if (d < PDD) pi[d] = pos[(b * NN + i) * PDD + d];
        else if (d < 2 * PDD) pj[d - PDD] = pos[(b * NN + j) * PDD + (d - PDD)];
        __syncthreads();
        float s = ge[b * DD + d] + peb[d];
        #pragma unroll
        for (int p = 0; p < PDD; p++) s += pi[p] * pew[p * DD + d];
        #pragma unroll
        for (int p = 0; p < PDD; p++) s += pj[p] * pew[(PDD + p) * DD + d];
        x[(size_t)tok * DD + d] = s;
    }
}

// -------------------- tf32 GEMM with 2-stage smem double buffering --------------------
// Block 256 thr (8 warps), tile 128(M) x 64(N), BK=32. Warp 32x32, m16n8k8.
#define GEMM_SM_BYTES ((2 * 128 * 36 + 2 * 32 * 72) * 4)

__global__ __launch_bounds__(256) void gemm_tf32_kernel(
    const float* __restrict__ A, const float* __restrict__ W,
    const float* __restrict__ bias, float* __restrict__ C,
    int M, int K, int N, int relu)
{
    extern __shared__ float smg[];
    float (*As)[36] = (float(*)[36])smg;                     // [2*128][36]
    float (*Bs)[72] = (float(*)[72])(smg + 2 * 128 * 36);    // [2*32][72]

    int tid = threadIdx.x;
    int warp = tid >> 5, lane = tid & 31;
    int g = lane >> 2, t = lane & 3;
    int wm = warp >> 1, wn = warp & 1;
    int m0 = wm * 32;
    int n0w = wn * 32;
    int brow0 = blockIdx.y * 128;
    int bcol0 = blockIdx.x * 64;

    float acc[2][4][4];
    #pragma unroll
    for (int mi = 0; mi < 2; mi++)
        #pragma unroll
        for (int ni = 0; ni < 4; ni++)
            #pragma unroll
            for (int v = 0; v < 4; v++) acc[mi][ni][v] = 0.f;

    int ar = tid >> 1;                 // 0..127
    int acb = (tid & 1) * 16;          // 0 or 16
    int grow = brow0 + ar;
    int nk = K >> 5;

    // prologue: tile 0 into buffer 0
    {
        #pragma unroll
        for (int i = 0; i < 4; i++) {
            int c = acb + i * 4;
            float4 v = make_float4(0.f, 0.f, 0.f, 0.f);
            if (grow < M) v = *(const float4*)(A + (size_t)grow * K + c);
            float4 w;
            w.x = to_tf32(v.x); w.y = to_tf32(v.y); w.z = to_tf32(v.z); w.w = to_tf32(v.w);
            *(float4*)&As[ar][c] = w;
        }
        #pragma unroll
        for (int i = 0; i < 2; i++) {
            int lin = tid * 2 + i;
            int br = lin >> 4;
            int c = (lin & 15) * 4;
            float4 v = *(const float4*)(W + (size_t)br * N + bcol0 + c);
            float4 w;
            w.x = to_tf32(v.x); w.y = to_tf32(v.y); w.z = to_tf32(v.z); w.w = to_tf32(v.w);
            *(float4*)&Bs[br][c] = w;
        }
    }
    __syncthreads();

    for (int kt = 0; kt < nk; kt++) {
        int cur = kt & 1;
        float4 pa[4], pb[2];
        bool pre = (kt + 1 < nk);
        if (pre) {
            int k0 = (kt + 1) << 5;
            #pragma unroll
            for (int i = 0; i < 4; i++) {
                int c = acb + i * 4;
                pa[i] = make_float4(0.f, 0.f, 0.f, 0.f);
                if (grow < M) pa[i] = *(const float4*)(A + (size_t)grow * K + k0 + c);
            }
            #pragma unroll
            for (int i = 0; i < 2; i++) {
                int lin = tid * 2 + i;
                int br = lin >> 4;
                int c = (lin & 15) * 4;
                pb[i] = *(const float4*)(W + (size_t)(k0 + br) * N + bcol0 + c);
            }
        }

        const float (*Ac)[36] = As + cur * 128;
        const float (*Bc)[72] = Bs + cur * 32;
        #pragma unroll
        for (int k8 = 0; k8 < 4; k8++) {
            int kk = k8 * 8;
            uint32_t afr[2][4];
            #pragma unroll
            for (int mi = 0; mi < 2; mi++) {
                int row = m0 + mi * 16;
                afr[mi][0] = __float_as_uint(Ac[row + g][kk + t]);
                afr[mi][1] = __float_as_uint(Ac[row + g + 8][kk + t]);
                afr[mi][2] = __float_as_uint(Ac[row + g][kk + t + 4]);
                afr[mi][3] = __float_as_uint(Ac[row + g + 8][kk + t + 4]);
            }
            uint32_t bfr[4][2];
            #pragma unroll
            for (int ni = 0; ni < 4; ni++) {
                int col = n0w + ni * 8;
                bfr[ni][0] = __float_as_uint(Bc[kk + t][col + g]);
                bfr[ni][1] = __float_as_uint(Bc[kk + t + 4][col + g]);
            }
            #pragma unroll
            for (int mi = 0; mi < 2; mi++)
                #pragma unroll
                for (int ni = 0; ni < 4; ni++)
                    mma_tf32(acc[mi][ni], afr[mi], bfr[ni]);
        }

        if (pre) {
            int nxt = cur ^ 1;
            #pragma unroll
            for (int i = 0; i < 4; i++) {
                int c = acb + i * 4;
                float4 w;
                w.x = to_tf32(pa[i].x); w.y = to_tf32(pa[i].y);
                w.z = to_tf32(pa[i].z); w.w = to_tf32(pa[i].w);
                *(float4*)&As[nxt * 128 + ar][c] = w;
            }
            #pragma unroll
            for (int i = 0; i < 2; i++) {
                int lin = tid * 2 + i;
                int br = lin >> 4;
                int c = (lin & 15) * 4;
                float4 w;
                w.x = to_tf32(pb[i].x); w.y = to_tf32(pb[i].y);
                w.z = to_tf32(pb[i].z); w.w = to_tf32(pb[i].w);
                *(float4*)&Bs[nxt * 32 + br][c] = w;
            }
        }
        __syncthreads();
    }

    // epilogue
    #pragma unroll
    for (int ni = 0; ni < 4; ni++) {
        int col = bcol0 + n0w + ni * 8 + 2 * t;
        float b0 = bias[col], b1 = bias[col + 1];
        #pragma unroll
        for (int mi = 0; mi < 2; mi++) {
            int row = brow0 + m0 + mi * 16 + g;
            float v0 = acc[mi][ni][0] + b0;
            float v1 = acc[mi][ni][1] + b1;
            float v2 = acc[mi][ni][2] + b0;
            float v3 = acc[mi][ni][3] + b1;
            if (relu) {
                v0 = fmaxf(v0, 0.f); v1 = fmaxf(v1, 0.f);
                v2 = fmaxf(v2, 0.f); v3 = fmaxf(v3, 0.f);
            }
            if (row < M)     { float2 p = make_float2(v0, v1); *(float2*)(C + (size_t)row * N + col) = p; }
            if (row + 8 < M) { float2 p = make_float2(v2, v3); *(float2*)(C + (size_t)(row + 8) * N + col) = p; }
        }
    }
}

// -------------------- tf32 flash attention, register softmax --------------------
// grid (QT2, HH, BB), 256 thr (8 warps). BQ=128 q-tile, 64-key tiles.
// Warp w owns q rows [w*16, w*16+16), full 64-key / 64-d width.
#define ATT_SM_FLOATS (2 * 128 * 68 + 64 * 68 + 64 * 72)
#define ATT_SM_BYTES (ATT_SM_FLOATS * 4)

__global__ __launch_bounds__(256, 2) void attn_mma_kernel(
    const float* __restrict__ Q, const float* __restrict__ Kmat,
    const float* __restrict__ V, float* __restrict__ O)
{
    extern __shared__ float sm[];
    float (*Qs)[68] = (float(*)[68])sm;                       // 128x68
    float (*Pw)[68] = (float(*)[68])(sm + 128 * 68);          // 128x68 (warp-private 16-row slices)
    float (*Ks)[68] = (float(*)[68])(sm + 2 * 128 * 68);      // 64x68 [key][d]
    float (*Vs)[72] = (float(*)[72])(sm + 2 * 128 * 68 + 64 * 68); // 64x72 [key][d]

    int b = blockIdx.z, h = blockIdx.y;
    int q0 = blockIdx.x * BQ;
    int tid = threadIdx.x;
    int warp = tid >> 5, lane = tid & 31;
    int g = lane >> 2, t = lane & 3;
    int mrow = warp * 16;

    const float* Qb = Q + (size_t)b * SS * 512 + h * 64;
    const float* Kb = Kmat + (size_t)b * SS * 512 + h * 64;
    const float* Vb = V + (size_t)b * SS * 512 + h * 64;

    // stage Q (scaled by 1/sqrt(64), tf32)
    {
        int r = tid >> 1;
        int cb = (tid & 1) * 32;
        #pragma unroll
        for (int i = 0; i < 8; i++) {
            int c = cb + i * 4;
            float4 v = make_float4(0.f, 0.f, 0.f, 0.f);
            if (q0 + r < SS) v = *(const float4*)(Qb + (size_t)(q0 + r) * 512 + c);
            float4 w;
            w.x = to_tf32(v.x * 0.125f); w.y = to_tf32(v.y * 0.125f);
            w.z = to_tf32(v.z * 0.125f); w.w = to_tf32(v.w * 0.125f);
            *(float4*)&Qs[r][c] = w;
        }
    }
    __syncthreads();

    float m0 = -1e30f, m1 = -1e30f, l0 = 0.f, l1 = 0.f;
    float accO[8][4];
    #pragma unroll
    for (int ni = 0; ni < 8; ni++)
        #pragma unroll
        for (int v = 0; v < 4; v++) accO[ni][v] = 0.f;

    for (int kt0 = 0; kt0 < SS; kt0 += 64) {
        // cooperative K/V load (tf32, zero-padded)
        {
            int r = tid >> 2;
            int cb = (tid & 3) * 16;
            #pragma unroll
            for (int i = 0; i < 4; i++) {
                int c = cb + i * 4;
                float4 kv = make_float4(0.f, 0.f, 0.f, 0.f);
                float4 vv = make_float4(0.f, 0.f, 0.f, 0.f);
                if (kt0 + r < SS) {
                    kv = *(const float4*)(Kb + (size_t)(kt0 + r) * 512 + c);
                    vv = *(const float4*)(Vb + (size_t)(kt0 + r) * 512 + c);
                }
                float4 kw, vw;
                kw.x = to_tf32(kv.x); kw.y = to_tf32(kv.y); kw.z = to_tf32(kv.z); kw.w = to_tf32(kv.w);
                vw.x = to_tf32(vv.x); vw.y = to_tf32(vv.y); vw.z = to_tf32(vv.z); vw.w = to_tf32(vv.w);
                *(float4*)&Ks[r][c] = kw;
                *(float4*)&Vs[r][c] = vw;
            }
        }
        __syncthreads();

        // ---- S = Q @ K^T ----
        float accS[8][4];
        #pragma unroll
        for (int ni = 0; ni < 8; ni++)
            #pragma unroll
            for (int v = 0; v < 4; v++) accS[ni][v] = 0.f;

        #pragma unroll
        for (int k8 = 0; k8 < 8; k8++) {
            int kk = k8 * 8;
            uint32_t afr[4];
            afr[0] = __float_as_uint(Qs[mrow + g][kk + t]);
            afr[1] = __float_as_uint(Qs[mrow + g + 8][kk + t]);
            afr[2] = __float_as_uint(Qs[mrow + g][kk + t + 4]);
            afr[3] = __float_as_uint(Qs[mrow + g + 8][kk + t + 4]);
            #pragma unroll
            for (int ni = 0; ni < 8; ni++) {
                uint32_t bfr[2];
                bfr[0] = __float_as_uint(Ks[ni * 8 + g][kk + t]);
                bfr[1] = __float_as_uint(Ks[ni * 8 + g][kk + t + 4]);
                mma_tf32(accS[ni], afr, bfr);
            }
        }

        // tail masking (only last tile)
        if (kt0 + 64 > SS) {
            #pragma unroll
            for (int ni = 0; ni < 8; ni++) {
                int c0 = kt0 + ni * 8 + 2 * t;
                if (c0 >= SS)     { accS[ni][0] = -1e30f; accS[ni][2] = -1e30f; }
                if (c0 + 1 >= SS) { accS[ni][1] = -1e30f; accS[ni][3] = -1e30f; }
            }
        }

        // ---- register online softmax (rows g and g+8; 4 lanes per row) ----
        float rx0 = -1e30f, rx1 = -1e30f;
        #pragma unroll
        for (int ni = 0; ni < 8; ni++) {
            rx0 = fmaxf(rx0, fmaxf(accS[ni][0], accS[ni][1]));
            rx1 = fmaxf(rx1, fmaxf(accS[ni][2], accS[ni][3]));
        }
        rx0 = fmaxf(rx0, __shfl_xor_sync(0xffffffffu, rx0, 1));
        rx0 = fmaxf(rx0, __shfl_xor_sync(0xffffffffu, rx0, 2));
        rx1 = fmaxf(rx1, __shfl_xor_sync(0xffffffffu, rx1, 1));
        rx1 = fmaxf(rx1, __shfl_xor_sync(0xffffffffu, rx1, 2));

        float mn0 = fmaxf(m0, rx0), mn1 = fmaxf(m1, rx1);
        float cr0 = __expf(m0 - mn0), cr1 = __expf(m1 - mn1);
        float rs0 = 0.f, rs1 = 0.f;
        #pragma unroll
        for (int ni = 0; ni < 8; ni++) {
            float p0 = __expf(accS[ni][0] - mn0);
            float p1 = __expf(accS[ni][1] - mn0);
            float p2 = __expf(accS[ni][2] - mn1);
            float p3 = __expf(accS[ni][3] - mn1);
            rs0 += p0 + p1;
            rs1 += p2 + p3;
            int col = ni * 8 + 2 * t;
            float2 w0 = make_float2(to_tf32(p0), to_tf32(p1));
            float2 w1 = make_float2(to_tf32(p2), to_tf32(p3));
            *(float2*)&Pw[mrow + g][col] = w0;
            *(float2*)&Pw[mrow + g + 8][col] = w1;
        }
        rs0 += __shfl_xor_sync(0xffffffffu, rs0, 1);
        rs0 += __shfl_xor_sync(0xffffffffu, rs0, 2);
        rs1 += __shfl_xor_sync(0xffffffffu, rs1, 1);
        rs1 += __shfl_xor_sync(0xffffffffu, rs1, 2);
        l0 = l0 * cr0 + rs0;
        l1 = l1 * cr1 + rs1;
        m0 = mn0; m1 = mn1;
        #pragma unroll
        for (int ni = 0; ni < 8; ni++) {
            accO[ni][0] *= cr0; accO[ni][1] *= cr0;
            accO[ni][2] *= cr1; accO[ni][3] *= cr1;
        }
        __syncwarp();

        // ---- O += P @ V ----
        #pragma unroll
        for (int k8 = 0; k8 < 8; k8++) {
            int kk = k8 * 8;
            uint32_t afr[4];
            afr[0] = __float_as_uint(Pw[mrow + g][kk + t]);
            afr[1] = __float_as_uint(Pw[mrow + g + 8][kk + t]);
            afr[2] = __float_as_uint(Pw[mrow + g][kk + t + 4]);
            afr[3] = __float_as_uint(Pw[mrow + g + 8][kk + t + 4]);
            #pragma unroll
            for (int ni = 0; ni < 8; ni++) {
                uint32_t bfr[2];
                bfr[0] = __float_as_uint(Vs[kk + t][ni * 8 + g]);
                bfr[1] = __float_as_uint(Vs[kk + t + 4][ni * 8 + g]);
                mma_tf32(accO[ni], afr, bfr);
            }
        }
        __syncthreads();
    }

    // store O / l
    float* Ob = O + (size_t)b * SS * 512 + h * 64;
    float inv0 = 1.f / l0, inv1 = 1.f / l1;
    int r1 = q0 + mrow + g;
    int r2 = r1 + 8;
    #pragma unroll
    for (int ni = 0; ni < 8; ni++) {
        int col = ni * 8 + 2 * t;
        if (r1 < SS) {
            float2 p = make_float2(accO[ni][0] * inv0, accO[ni][1] * inv0);
            *(float2*)(Ob + (size_t)r1 * 512 + col) = p;
        }
        if (r2 < SS) {
            float2 p = make_float2(accO[ni][2] * inv1, accO[ni][3] * inv1);
            *(float2*)(Ob + (size_t)r2 * 512 + col) = p;
        }
    }
}

// -------------------- x = LayerNorm(x + h) --------------------
__global__ void add_ln_kernel(float* __restrict__ x, const float* __restrict__ h,
                              const float* __restrict__ g, const float* __restrict__ bb)
{
    int row = blockIdx.x, t = threadIdx.x;
    float v = x[(size_t)row * DD + t] + h[(size_t)row * DD + t];
    float s1 = v, s2 = v * v;
    #pragma unroll
    for (int o = 16; o; o >>= 1) {
        s1 += __shfl_xor_sync(0xffffffffu, s1, o);
        s2 += __shfl_xor_sync(0xffffffffu, s2, o);
    }
    __shared__ float r1[8], r2[8];
    int w = t >> 5, ln = t & 31;
    if (ln == 0) { r1[w] = s1; r2[w] = s2; }
    __syncthreads();
    if (w == 0) {
        float a = (ln < 8) ? r1[ln] : 0.f;
        float c = (ln < 8) ? r2[ln] : 0.f;
        #pragma unroll
        for (int o = 4; o; o >>= 1) {
            a += __shfl_xor_sync(0xffffffffu, a, o);
            c += __shfl_xor_sync(0xffffffffu, c, o);
        }
        if (ln == 0) { r1[0] = a; r2[0] = c; }
    }
    __syncthreads();
    float mean = r1[0] * (1.f / 256.f);
    float var = r2[0] * (1.f / 256.f) - mean * mean;
    float rstd = rsqrtf(var + 1e-5f);
    x[(size_t)row * DD + t] = (v - mean) * rstd * g[t] + bb[t];
}

// -------------------- output heads --------------------
__global__ void node_out_kernel(const float* __restrict__ x, const float* __restrict__ w,
                                const float* __restrict__ bias, float* __restrict__ out)
{
    int idx = blockIdx.x;
    int b = idx / NN, i = idx % NN;
    int t = threadIdx.x;
    __shared__ float xr[DD];
    xr[t] = x[(size_t)(b * SS + i) * DD + t];
    __syncthreads();
    int wrp = t >> 5, ln = t & 31;
    #pragma unroll
    for (int cb = 0; cb < 24; cb += 8) {
        int c = cb + wrp;
        float s = 0.f;
        if (c < NFD) {
            #pragma unroll
            for (int k = 0; k < 8; k++) s += xr[ln + 32 * k] * w[(ln + 32 * k) * NFD + c];
        }
        #pragma unroll
        for (int o = 16; o; o >>= 1) s += __shfl_xor_sync(0xffffffffu, s, o);
        if (ln == 0 && c < NFD) out[(size_t)idx * NFD + c] = s + bias[c];
    }
}

__global__ void edge_out_kernel(const float* __restrict__ x, const float* __restrict__ w,
                                const float* __restrict__ bias, float* __restrict__ out)
{
    int idx = blockIdx.x;
    int b = idx / (NN * NN);
    int r = idx % (NN * NN);
    int i = r / NN, j = r % NN;
    int t = threadIdx.x;
    __shared__ float sr[DD];
    const float* xi = x + (size_t)(b * SS + NN + i * NN + j) * DD;
    const float* xj = x + (size_t)(b * SS + NN + j * NN + i) * DD;
    sr[t] = xi[t] + xj[t];
    __syncthreads();
    int wrp = t >> 5, ln = t & 31;
    int c = wrp;
    float s = 0.f;
    if (c < NED) {
        #pragma unroll
        for (int k = 0; k < 8; k++) s += sr[ln + 32 * k] * w[(ln + 32 * k) * NED + c];
    }
    #pragma unroll
    for (int o = 16; o; o >>= 1) s += __shfl_xor_sync(0xffffffffu, s, o);
    if (ln == 0 && c < NED) out[(size_t)idx * NED + c] = 0.5f * s + bias[c];
}

// -------------------- host orchestration --------------------
static inline float* sym_addr(const void* sym)
{
    void* p = nullptr;
    cudaGetSymbolAddress(&p, sym);
    return (float*)p;
}

extern "C" void kernel_launch(void* const* d_in, const int* in_sizes, int n_in,
                              void* d_out, int out_size)
{
    (void)in_sizes; (void)n_in; (void)out_size;
    const float* graph_emb = (const float*)d_in[0];
    const float* perm      = (const float*)d_in[1];
    const float* pnw = (const float*)d_in[3];
    const float* pnb = (const float*)d_in[4];
    const float* pew = (const float*)d_in[5];
    const float* peb = (const float*)d_in[6];
    const float* now_ = (const float*)d_in[7];
    const float* nob = (const float*)d_in[8];
    const float* eow = (const float*)d_in[9];
    const float* eob = (const float*)d_in[10];
    const float* Wq = (const float*)d_in[11];
    const float* bq = (const float*)d_in[12];
    const float* Wk = (const float*)d_in[13];
    const float* bk = (const float*)d_in[14];
    const float* Wv = (const float*)d_in[15];
    const float* bv = (const float*)d_in[16];
    const float* Wo = (const float*)d_in[17];
    const float* bo = (const float*)d_in[18];
    const float* W1 = (const float*)d_in[19];
    const float* b1 = (const float*)d_in[20];
    const float* W2 = (const float*)d_in[21];
    const float* b2 = (const float*)d_in[22];
    const float* ln1g = (const float*)d_in[23];
    const float* ln1b = (const float*)d_in[24];
    const float* ln2g = (const float*)d_in[25];
    const float* ln2b = (const float*)d_in[26];

    float* px   = sym_addr(g_x);
    float* ppos = sym_addr(g_pos);
    float* pq   = sym_addr(g_q);
    float* pk   = sym_addr(g_k);
    float* pv   = sym_addr(g_v);
    float* pat  = sym_addr(g_attn);
    float* pt   = sym_addr(g_t);
    float* pff  = sym_addr(g_ff);

    cudaFuncSetAttribute(attn_mma_kernel, cudaFuncAttributeMaxDynamicSharedMemorySize, ATT_SM_BYTES);
    cudaFuncSetAttribute(gemm_tf32_kernel, cudaFuncAttributeMaxDynamicSharedMemorySize, GEMM_SM_BYTES);

    const int MROWS = BS;                   // 4704
    const int MT128 = (MROWS + 127) / 128;  // 37

    pos_kernel<<<BB * NN, 32>>>(perm, ppos);
    embed_kernel<<<BS, 256>>>(graph_emb, ppos, pnw, pnb, pew, peb, px);

    for (int l = 0; l < LL; l++) {
        const float* wq = Wq + (size_t)l * DD * 512;
        const float* wk = Wk + (size_t)l * DD * 512;
        const float* wv = Wv + (size_t)l * DD * 512;
        const float* wo = Wo + (size_t)l * 512 * DD;
        const float* w1 = W1 + (size_t)l * DD * FFD;
        const float* w2 = W2 + (size_t)l * FFD * DD;

        gemm_tf32_kernel<<<dim3(512 / 64, MT128), 256, GEMM_SM_BYTES>>>(px, wq, bq + l * 512, pq, MROWS, DD, 512, 0);
        gemm_tf32_kernel<<<dim3(512 / 64, MT128), 256, GEMM_SM_BYTES>>>(px, wk, bk + l * 512, pk, MROWS, DD, 512, 0);
        gemm_tf32_kernel<<<dim3(512 / 64, MT128), 256, GEMM_SM_BYTES>>>(px, wv, bv + l * 512, pv, MROWS, DD, 512, 0);

        attn_mma_kernel<<<dim3(QT2, HH, BB), 256, ATT_SM_BYTES>>>(pq, pk, pv, pat);

        gemm_tf32_kernel<<<dim3(DD / 64, MT128), 256, GEMM_SM_BYTES>>>(pat, wo, bo + l * DD, pt, MROWS, 512, DD, 0);
        add_ln_kernel<<<BS, 256>>>(px, pt, ln1g + l * DD, ln1b + l * DD);

        gemm_tf32_kernel<<<dim3(FFD / 64, MT128), 256, GEMM_SM_BYTES>>>(px, w1, b1 + l * FFD, pff, MROWS, DD, FFD, 1);
        gemm_tf32_kernel<<<dim3(DD / 64, MT128), 256, GEMM_SM_BYTES>>>(pff, w2, b2 + l * DD, pt, MROWS, FFD, DD, 0);
        add_ln_kernel<<<BS, 256>>>(px, pt, ln2g + l * DD, ln2b + l * DD);
    }

    float* out = (float*)d_out;
    node_out_kernel<<<BB * NN, 256>>>(px, now_, nob, out);
    edge_out_kernel<<<BB * NN * NN, 256>>>(px, eow, eob, out + BB * NN * NFD);
}

// round 6
// speedup vs baseline: 17.1602x; 1.1143x over previous
#include <cuda_runtime.h>
#include <cuda_bf16.h>
#include <math.h>
#include <stdint.h>

// Problem constants
#define BB 2
#define NN 48
#define DD 256
#define HH 8
#define DKV 64
#define FFD 1024
#define LL 4
#define PDD 32
#define NFD 20
#define NED 5
#define SS 2352           // NN + NN*NN
#define BS 4704           // BB*SS
#define BQ 128
#define QT2 ((SS + BQ - 1) / BQ)   // 19
#define NKT ((SS + 63) / 64)       // 37 key tiles

// -------------------- scratch (device globals; no allocation) --------------------
__device__ float g_pos[BB * NN * PDD];
__device__ float g_x[BS * DD];
__device__ float g_q[BS * HH * DKV];
__device__ float g_k[BS * HH * DKV];
__device__ float g_v[BS * HH * DKV];
__device__ float g_attn[BS * HH * DKV];
__device__ float g_t[BS * DD];
__device__ float g_ff[BS * FFD];

// -------------------- helpers --------------------
__device__ __forceinline__ float to_tf32(float x)
{
    uint32_t u;
    asm("cvt.rna.tf32.f32 %0, %1;" : "=r"(u) : "f"(x));
    return __uint_as_float(u);
}

__device__ __forceinline__ uint32_t to_tf32u(float x)
{
    uint32_t u;
    asm("cvt.rna.tf32.f32 %0, %1;" : "=r"(u) : "f"(x));
    return u;
}

__device__ __forceinline__ void mma_tf32(float* d, const uint32_t* a, const uint32_t* b)
{
    asm volatile(
        "mma.sync.aligned.m16n8k8.row.col.f32.tf32.tf32.f32 "
        "{%0,%1,%2,%3}, {%4,%5,%6,%7}, {%8,%9}, {%0,%1,%2,%3};"
        : "+f"(d[0]), "+f"(d[1]), "+f"(d[2]), "+f"(d[3])
        : "r"(a[0]), "r"(a[1]), "r"(a[2]), "r"(a[3]), "r"(b[0]), "r"(b[1]));
}

__device__ __forceinline__ void cp_async16(void* smem_dst, const void* gmem_src, bool valid)
{
    uint32_t s = (uint32_t)__cvta_generic_to_shared(smem_dst);
    int sz = valid ? 16 : 0;
    asm volatile("cp.async.cg.shared.global [%0], [%1], 16, %2;\n"
                 :: "r"(s), "l"(gmem_src), "r"(sz));
}

__device__ __forceinline__ void cp_commit() { asm volatile("cp.async.commit_group;\n" ::); }
__device__ __forceinline__ void cp_wait0()  { asm volatile("cp.async.wait_group 0;\n" ::); }

// -------------------- pos = perm @ posenc --------------------
__global__ void pos_kernel(const float* __restrict__ perm, float* __restrict__ pos)
{
    int row = blockIdx.x;
    int d = threadIdx.x;
    const float* pr = perm + (size_t)row * NN;
    float freq = expf(-logf(10000.f) * (float)(d & ~1) / (float)PDD);
    float s = 0.f;
    #pragma unroll 8
    for (int j = 0; j < NN; j++) {
        float ang = (float)j * freq;
        float pe = (d & 1) ? cosf(ang) : sinf(ang);
        s += pr[j] * pe;
    }
    pos[row * PDD + d] = s;
}

// -------------------- token embedding --------------------
__global__ void embed_kernel(const float* __restrict__ ge, const float* __restrict__ pos,
                             const float* __restrict__ pnw, const float* __restrict__ pnb,
                             const float* __restrict__ pew, const float* __restrict__ peb,
                             float* __restrict__ x)
{
    int tok = blockIdx.x;
    int b = tok / SS;
    int r = tok % SS;
    int d = threadIdx.x;
    __shared__ float pi[PDD];
    __shared__ float pj[PDD];

    if (r < NN) {
        if (d < PDD) pi[d] = pos[(b * NN + r) * PDD + d];
        __syncthreads();
        float s = ge[b * DD + d] + pnb[d];
        #pragma unroll
        for (int p = 0; p < PDD; p++) s += pi[p] * pnw[p * DD + d];
        x[(size_t)tok * DD + d] = s;
    } else {
        int e = r - NN;
        int i = e / NN, j = e % NN;
        if (d < PDD) pi[d] = pos[(b * NN + i) * PDD + d];
        else if (d < 2 * PDD) pj[d - PDD] = pos[(b * NN + j) * PDD + (d - PDD)];
        __syncthreads();
        float s = ge[b * DD + d] + peb[d];
        #pragma unroll
        for (int p = 0; p < PDD; p++) s += pi[p] * pew[p * DD + d];
        #pragma unroll
        for (int p = 0; p < PDD; p++) s += pj[p] * pew[(PDD + p) * DD + d];
        x[(size_t)tok * DD + d] = s;
    }
}

// -------------------- tf32 GEMM, cp.async double-buffered --------------------
// Block 256 thr (8 warps), tile 128(M) x 64(N), BK=32. Warp 32x32, m16n8k8.
// Raw fp32 lands in smem via cp.async; rna-tf32 rounding applied at
// fragment-build time (restores round-to-nearest numerics).
#define GEMM_SM_FLOATS (2 * 128 * 36 + 2 * 32 * 72)
#define GEMM_SM_BYTES (GEMM_SM_FLOATS * 4)

__global__ __launch_bounds__(256, 3) void gemm_tf32_kernel(
    const float* __restrict__ A, const float* __restrict__ W,
    const float* __restrict__ bias, float* __restrict__ C,
    int M, int K, int N, int relu)
{
    extern __shared__ float smg[];
    float (*As)[36] = (float(*)[36])smg;                     // [2*128][36]
    float (*Bs)[72] = (float(*)[72])(smg + 2 * 128 * 36);    // [2*32][72]

    int tid = threadIdx.x;
    int warp = tid >> 5, lane = tid & 31;
    int g = lane >> 2, t = lane & 3;
    int wm = warp >> 1, wn = warp & 1;
    int m0 = wm * 32;
    int n0w = wn * 32;
    int brow0 = blockIdx.y * 128;
    int bcol0 = blockIdx.x * 64;

    float acc[2][4][4];
    #pragma unroll
    for (int mi = 0; mi < 2; mi++)
        #pragma unroll
        for (int ni = 0; ni < 4; ni++)
            #pragma unroll
            for (int v = 0; v < 4; v++) acc[mi][ni][v] = 0.f;

    // load assignment
    int a_row = tid >> 1;                   // 0..127
    int a_cb  = (tid & 1) * 16;             // float col base
    int grow  = brow0 + a_row;
    bool a_ok = grow < M;
    const float* a_src = A + (size_t)(a_ok ? grow : 0) * K;
    int nk = K >> 5;

    // prologue: tile 0 -> buffer 0
    {
        #pragma unroll
        for (int i = 0; i < 4; i++)
            cp_async16(&As[a_row][a_cb + i * 4], a_src + a_cb + i * 4, a_ok);
        #pragma unroll
        for (int i = 0; i < 2; i++) {
            int lin = tid * 2 + i;
            int br = lin >> 4;
            int c = (lin & 15) * 4;
            cp_async16(&Bs[br][c], W + (size_t)br * N + bcol0 + c, true);
        }
        cp_commit();
    }

    for (int kt = 0; kt < nk; kt++) {
        cp_wait0();
        __syncthreads();

        if (kt + 1 < nk) {
            int k0 = (kt + 1) << 5;
            int nb = ((kt + 1) & 1);
            #pragma unroll
            for (int i = 0; i < 4; i++)
                cp_async16(&As[nb * 128 + a_row][a_cb + i * 4], a_src + k0 + a_cb + i * 4, a_ok);
            #pragma unroll
            for (int i = 0; i < 2; i++) {
                int lin = tid * 2 + i;
                int br = lin >> 4;
                int c = (lin & 15) * 4;
                cp_async16(&Bs[nb * 32 + br][c], W + (size_t)(k0 + br) * N + bcol0 + c, true);
            }
            cp_commit();
        }

        const float (*Ac)[36] = As + (kt & 1) * 128;
        const float (*Bc)[72] = Bs + (kt & 1) * 32;
        #pragma unroll
        for (int k8 = 0; k8 < 4; k8++) {
            int kk = k8 * 8;
            uint32_t afr[2][4];
            #pragma unroll
            for (int mi = 0; mi < 2; mi++) {
                int row = m0 + mi * 16;
                afr[mi][0] = to_tf32u(Ac[row + g][kk + t]);
                afr[mi][1] = to_tf32u(Ac[row + g + 8][kk + t]);
                afr[mi][2] = to_tf32u(Ac[row + g][kk + t + 4]);
                afr[mi][3] = to_tf32u(Ac[row + g + 8][kk + t + 4]);
            }
            uint32_t bfr[4][2];
            #pragma unroll
            for (int ni = 0; ni < 4; ni++) {
                int col = n0w + ni * 8;
                bfr[ni][0] = to_tf32u(Bc[kk + t][col + g]);
                bfr[ni][1] = to_tf32u(Bc[kk + t + 4][col + g]);
            }
            #pragma unroll
            for (int mi = 0; mi < 2; mi++)
                #pragma unroll
                for (int ni = 0; ni < 4; ni++)
                    mma_tf32(acc[mi][ni], afr[mi], bfr[ni]);
        }
    }

    // epilogue
    #pragma unroll
    for (int ni = 0; ni < 4; ni++) {
        int col = bcol0 + n0w + ni * 8 + 2 * t;
        float b0 = bias[col], b1 = bias[col + 1];
        #pragma unroll
        for (int mi = 0; mi < 2; mi++) {
            int row = brow0 + m0 + mi * 16 + g;
            float v0 = acc[mi][ni][0] + b0;
            float v1 = acc[mi][ni][1] + b1;
            float v2 = acc[mi][ni][2] + b0;
            float v3 = acc[mi][ni][3] + b1;
            if (relu) {
                v0 = fmaxf(v0, 0.f); v1 = fmaxf(v1, 0.f);
                v2 = fmaxf(v2, 0.f); v3 = fmaxf(v3, 0.f);
            }
            if (row < M)     { float2 p = make_float2(v0, v1); *(float2*)(C + (size_t)row * N + col) = p; }
            if (row + 8 < M) { float2 p = make_float2(v2, v3); *(float2*)(C + (size_t)(row + 8) * N + col) = p; }
        }
    }
}

// -------------------- tf32 flash attention --------------------
// grid (QT2, HH, BB), 256 thr (8 warps). BQ=128 q-tile, 64-key tiles,
// cp.async double-buffered K/V, register softmax, shuffle-built P fragments.
// rna-tf32 rounding applied at fragment-build time for K and V.
#define ATT_SM_FLOATS (128 * 68 + 2 * 64 * 68 + 2 * 64 * 72)
#define ATT_SM_BYTES (ATT_SM_FLOATS * 4)

__global__ __launch_bounds__(256, 2) void attn_mma_kernel(
    const float* __restrict__ Q, const float* __restrict__ Kmat,
    const float* __restrict__ V, float* __restrict__ O)
{
    extern __shared__ float sm[];
    float (*Qs)[68] = (float(*)[68])sm;                          // 128x68
    float (*Ks)[68] = (float(*)[68])(sm + 128 * 68);             // [2*64][68]
    float (*Vs)[72] = (float(*)[72])(sm + 128 * 68 + 2 * 64 * 68); // [2*64][72]

    int b = blockIdx.z, h = blockIdx.y;
    int q0 = blockIdx.x * BQ;
    int tid = threadIdx.x;
    int warp = tid >> 5, lane = tid & 31;
    int g = lane >> 2, t = lane & 3;
    int mrow = warp * 16;

    const float* Qb = Q + (size_t)b * SS * 512 + h * 64;
    const float* Kb = Kmat + (size_t)b * SS * 512 + h * 64;
    const float* Vb = V + (size_t)b * SS * 512 + h * 64;

    // K/V cp.async load assignment: 4 threads per row, 16 floats each
    int kv_row = tid >> 2;
    int kv_cb  = (tid & 3) * 16;

    // prologue: issue K/V tile 0 into buffer 0
    {
        bool ok = kv_row < SS;
        const float* ks = Kb + (size_t)(ok ? kv_row : 0) * 512 + kv_cb;
        const float* vs = Vb + (size_t)(ok ? kv_row : 0) * 512 + kv_cb;
        #pragma unroll
        for (int i = 0; i < 4; i++) {
            cp_async16(&Ks[kv_row][kv_cb + i * 4], ks + i * 4, ok);
            cp_async16(&Vs[kv_row][kv_cb + i * 4], vs + i * 4, ok);
        }
        cp_commit();
    }

    // stage Q (scaled by 1/sqrt(64), tf32-rounded)
    {
        int r = tid >> 1;
        int cb = (tid & 1) * 32;
        #pragma unroll
        for (int i = 0; i < 8; i++) {
            int c = cb + i * 4;
            float4 v = make_float4(0.f, 0.f, 0.f, 0.f);
            if (q0 + r < SS) v = *(const float4*)(Qb + (size_t)(q0 + r) * 512 + c);
            float4 w;
            w.x = to_tf32(v.x * 0.125f); w.y = to_tf32(v.y * 0.125f);
            w.z = to_tf32(v.z * 0.125f); w.w = to_tf32(v.w * 0.125f);
            *(float4*)&Qs[r][c] = w;
        }
    }

    float m0 = -1e30f, m1 = -1e30f, l0 = 0.f, l1 = 0.f;
    float accO[8][4];
    #pragma unroll
    for (int ni = 0; ni < 8; ni++)
        #pragma unroll
        for (int v = 0; v < 4; v++) accO[ni][v] = 0.f;

    int srcA = (lane & ~3) | (t >> 1);
    int srcB = srcA + 2;
    bool odd = (t & 1);

    for (int kt = 0; kt < NKT; kt++) {
        int kt0 = kt * 64;
        cp_wait0();
        __syncthreads();

        if (kt + 1 < NKT) {
            int nb = (kt + 1) & 1;
            int grow = kt0 + 64 + kv_row;
            bool ok = grow < SS;
            const float* ks = Kb + (size_t)(ok ? grow : 0) * 512 + kv_cb;
            const float* vs = Vb + (size_t)(ok ? grow : 0) * 512 + kv_cb;
            #pragma unroll
            for (int i = 0; i < 4; i++) {
                cp_async16(&Ks[nb * 64 + kv_row][kv_cb + i * 4], ks + i * 4, ok);
                cp_async16(&Vs[nb * 64 + kv_row][kv_cb + i * 4], vs + i * 4, ok);
            }
            cp_commit();
        }

        const float (*Kc)[68] = Ks + (kt & 1) * 64;
        const float (*Vc)[72] = Vs + (kt & 1) * 64;

        // ---- S = Q @ K^T ----
        float accS[8][4];
        #pragma unroll
        for (int ni = 0; ni < 8; ni++)
            #pragma unroll
            for (int v = 0; v < 4; v++) accS[ni][v] = 0.f;

        #pragma unroll
        for (int k8 = 0; k8 < 8; k8++) {
            int kk = k8 * 8;
            uint32_t afr[4];
            afr[0] = __float_as_uint(Qs[mrow + g][kk + t]);
            afr[1] = __float_as_uint(Qs[mrow + g + 8][kk + t]);
            afr[2] = __float_as_uint(Qs[mrow + g][kk + t + 4]);
            afr[3] = __float_as_uint(Qs[mrow + g + 8][kk + t + 4]);
            #pragma unroll
            for (int ni = 0; ni < 8; ni++) {
                uint32_t bfr[2];
                bfr[0] = to_tf32u(Kc[ni * 8 + g][kk + t]);
                bfr[1] = to_tf32u(Kc[ni * 8 + g][kk + t + 4]);
                mma_tf32(accS[ni], afr, bfr);
            }
        }

        // tail masking (only last tile)
        if (kt0 + 64 > SS) {
            #pragma unroll
            for (int ni = 0; ni < 8; ni++) {
                int c0 = kt0 + ni * 8 + 2 * t;
                if (c0 >= SS)     { accS[ni][0] = -1e30f; accS[ni][2] = -1e30f; }
                if (c0 + 1 >= SS) { accS[ni][1] = -1e30f; accS[ni][3] = -1e30f; }
            }
        }

        // ---- register online softmax (rows g and g+8; 4 lanes per row) ----
        float rx0 = -1e30f, rx1 = -1e30f;
        #pragma unroll
        for (int ni = 0; ni < 8; ni++) {
            rx0 = fmaxf(rx0, fmaxf(accS[ni][0], accS[ni][1]));
            rx1 = fmaxf(rx1, fmaxf(accS[ni][2], accS[ni][3]));
        }
        rx0 = fmaxf(rx0, __shfl_xor_sync(0xffffffffu, rx0, 1));
        rx0 = fmaxf(rx0, __shfl_xor_sync(0xffffffffu, rx0, 2));
        rx1 = fmaxf(rx1, __shfl_xor_sync(0xffffffffu, rx1, 1));
        rx1 = fmaxf(rx1, __shfl_xor_sync(0xffffffffu, rx1, 2));

        float mn0 = fmaxf(m0, rx0), mn1 = fmaxf(m1, rx1);
        float cr0 = __expf(m0 - mn0), cr1 = __expf(m1 - mn1);
        float rs0 = 0.f, rs1 = 0.f;
        #pragma unroll
        for (int ni = 0; ni < 8; ni++) {
            float p0 = __expf(accS[ni][0] - mn0);
            float p1 = __expf(accS[ni][1] - mn0);
            float p2 = __expf(accS[ni][2] - mn1);
            float p3 = __expf(accS[ni][3] - mn1);
            rs0 += p0 + p1;
            rs1 += p2 + p3;
            accS[ni][0] = to_tf32(p0);
            accS[ni][1] = to_tf32(p1);
            accS[ni][2] = to_tf32(p2);
            accS[ni][3] = to_tf32(p3);
        }
        rs0 += __shfl_xor_sync(0xffffffffu, rs0, 1);
        rs0 += __shfl_xor_sync(0xffffffffu, rs0, 2);
        rs1 += __shfl_xor_sync(0xffffffffu, rs1, 1);
        rs1 += __shfl_xor_sync(0xffffffffu, rs1, 2);
        l0 = l0 * cr0 + rs0;
        l1 = l1 * cr1 + rs1;
        m0 = mn0; m1 = mn1;
        #pragma unroll
        for (int ni = 0; ni < 8; ni++) {
            accO[ni][0] *= cr0; accO[ni][1] *= cr0;
            accO[ni][2] *= cr1; accO[ni][3] *= cr1;
        }

        // ---- O += P @ V, P fragments built via shuffles from accS ----
        #pragma unroll
        for (int k8 = 0; k8 < 8; k8++) {
            int kk = k8 * 8;
            float c0a = __shfl_sync(0xffffffffu, accS[k8][0], srcA);
            float c1a = __shfl_sync(0xffffffffu, accS[k8][1], srcA);
            float c2a = __shfl_sync(0xffffffffu, accS[k8][2], srcA);
            float c3a = __shfl_sync(0xffffffffu, accS[k8][3], srcA);
            float c0b = __shfl_sync(0xffffffffu, accS[k8][0], srcB);
            float c1b = __shfl_sync(0xffffffffu, accS[k8][1], srcB);
            float c2b = __shfl_sync(0xffffffffu, accS[k8][2], srcB);
            float c3b = __shfl_sync(0xffffffffu, accS[k8][3], srcB);
            uint32_t afr[4];
            afr[0] = __float_as_uint(odd ? c1a : c0a);   // (row g,   col kk+t)
            afr[1] = __float_as_uint(odd ? c3a : c2a);   // (row g+8, col kk+t)
            afr[2] = __float_as_uint(odd ? c1b : c0b);   // (row g,   col kk+t+4)
            afr[3] = __float_as_uint(odd ? c3b : c2b);   // (row g+8, col kk+t+4)
            #pragma unroll
            for (int ni = 0; ni < 8; ni++) {
                uint32_t bfr[2];
                bfr[0] = to_tf32u(Vc[kk + t][ni * 8 + g]);
                bfr[1] = to_tf32u(Vc[kk + t + 4][ni * 8 + g]);
                mma_tf32(accO[ni], afr, bfr);
            }
        }
    }

    // store O / l
    float* Ob = O + (size_t)b * SS * 512 + h * 64;
    float inv0 = 1.f / l0, inv1 = 1.f / l1;
    int r1 = q0 + mrow + g;
    int r2 = r1 + 8;
    #pragma unroll
    for (int ni = 0; ni < 8; ni++) {
        int col = ni * 8 + 2 * t;
        if (r1 < SS) {
            float2 p = make_float2(accO[ni][0] * inv0, accO[ni][1] * inv0);
            *(float2*)(Ob + (size_t)r1 * 512 + col) = p;
        }
        if (r2 < SS) {
            float2 p = make_float2(accO[ni][2] * inv1, accO[ni][3] * inv1);
            *(float2*)(Ob + (size_t)r2 * 512 + col) = p;
        }
    }
}

// -------------------- x = LayerNorm(x + h) --------------------
__global__ void add_ln_kernel(float* __restrict__ x, const float* __restrict__ h,
                              const float* __restrict__ g, const float* __restrict__ bb)
{
    int row = blockIdx.x, t = threadIdx.x;
    float v = x[(size_t)row * DD + t] + h[(size_t)row * DD + t];
    float s1 = v, s2 = v * v;
    #pragma unroll
    for (int o = 16; o; o >>= 1) {
        s1 += __shfl_xor_sync(0xffffffffu, s1, o);
        s2 += __shfl_xor_sync(0xffffffffu, s2, o);
    }
    __shared__ float r1[8], r2[8];
    int w = t >> 5, ln = t & 31;
    if (ln == 0) { r1[w] = s1; r2[w] = s2; }
    __syncthreads();
    if (w == 0) {
        float a = (ln < 8) ? r1[ln] : 0.f;
        float c = (ln < 8) ? r2[ln] : 0.f;
        #pragma unroll
        for (int o = 4; o; o >>= 1) {
            a += __shfl_xor_sync(0xffffffffu, a, o);
            c += __shfl_xor_sync(0xffffffffu, c, o);
        }
        if (ln == 0) { r1[0] = a; r2[0] = c; }
    }
    __syncthreads();
    float mean = r1[0] * (1.f / 256.f);
    float var = r2[0] * (1.f / 256.f) - mean * mean;
    float rstd = rsqrtf(var + 1e-5f);
    x[(size_t)row * DD + t] = (v - mean) * rstd * g[t] + bb[t];
}

// -------------------- output heads --------------------
__global__ void node_out_kernel(const float* __restrict__ x, const float* __restrict__ w,
                                const float* __restrict__ bias, float* __restrict__ out)
{
    int idx = blockIdx.x;
    int b = idx / NN, i = idx % NN;
    int t = threadIdx.x;
    __shared__ float xr[DD];
    xr[t] = x[(size_t)(b * SS + i) * DD + t];
    __syncthreads();
    int wrp = t >> 5, ln = t & 31;
    #pragma unroll
    for (int cb = 0; cb < 24; cb += 8) {
        int c = cb + wrp;
        float s = 0.f;
        if (c < NFD) {
            #pragma unroll
            for (int k = 0; k < 8; k++) s += xr[ln + 32 * k] * w[(ln + 32 * k) * NFD + c];
        }
        #pragma unroll
        for (int o = 16; o; o >>= 1) s += __shfl_xor_sync(0xffffffffu, s, o);
        if (ln == 0 && c < NFD) out[(size_t)idx * NFD + c] = s + bias[c];
    }
}

__global__ void edge_out_kernel(const float* __restrict__ x, const float* __restrict__ w,
                                const float* __restrict__ bias, float* __restrict__ out)
{
    int idx = blockIdx.x;
    int b = idx / (NN * NN);
    int r = idx % (NN * NN);
    int i = r / NN, j = r % NN;
    int t = threadIdx.x;
    __shared__ float sr[DD];
    const float* xi = x + (size_t)(b * SS + NN + i * NN + j) * DD;
    const float* xj = x + (size_t)(b * SS + NN + j * NN + i) * DD;
    sr[t] = xi[t] + xj[t];
    __syncthreads();
    int wrp = t >> 5, ln = t & 31;
    int c = wrp;
    float s = 0.f;
    if (c < NED) {
        #pragma unroll
        for (int k = 0; k < 8; k++) s += sr[ln + 32 * k] * w[(ln + 32 * k) * NED + c];
    }
    #pragma unroll
    for (int o = 16; o; o >>= 1) s += __shfl_xor_sync(0xffffffffu, s, o);
    if (ln == 0 && c < NED) out[(size_t)idx * NED + c] = 0.5f * s + bias[c];
}

// -------------------- host orchestration --------------------
static inline float* sym_addr(const void* sym)
{
    void* p = nullptr;
    cudaGetSymbolAddress(&p, sym);
    return (float*)p;
}

extern "C" void kernel_launch(void* const* d_in, const int* in_sizes, int n_in,
                              void* d_out, int out_size)
{
    (void)in_sizes; (void)n_in; (void)out_size;
    const float* graph_emb = (const float*)d_in[0];
    const float* perm      = (const float*)d_in[1];
    const float* pnw = (const float*)d_in[3];
    const float* pnb = (const float*)d_in[4];
    const float* pew = (const float*)d_in[5];
    const float* peb = (const float*)d_in[6];
    const float* now_ = (const float*)d_in[7];
    const float* nob = (const float*)d_in[8];
    const float* eow = (const float*)d_in[9];
    const float* eob = (const float*)d_in[10];
    const float* Wq = (const float*)d_in[11];
    const float* bq = (const float*)d_in[12];
    const float* Wk = (const float*)d_in[13];
    const float* bk = (const float*)d_in[14];
    const float* Wv = (const float*)d_in[15];
    const float* bv = (const float*)d_in[16];
    const float* Wo = (const float*)d_in[17];
    const float* bo = (const float*)d_in[18];
    const float* W1 = (const float*)d_in[19];
    const float* b1 = (const float*)d_in[20];
    const float* W2 = (const float*)d_in[21];
    const float* b2 = (const float*)d_in[22];
    const float* ln1g = (const float*)d_in[23];
    const float* ln1b = (const float*)d_in[24];
    const float* ln2g = (const float*)d_in[25];
    const float* ln2b = (const float*)d_in[26];

    float* px   = sym_addr(g_x);
    float* ppos = sym_addr(g_pos);
    float* pq   = sym_addr(g_q);
    float* pk   = sym_addr(g_k);
    float* pv   = sym_addr(g_v);
    float* pat  = sym_addr(g_attn);
    float* pt   = sym_addr(g_t);
    float* pff  = sym_addr(g_ff);

    cudaFuncSetAttribute(attn_mma_kernel, cudaFuncAttributeMaxDynamicSharedMemorySize, ATT_SM_BYTES);
    cudaFuncSetAttribute(gemm_tf32_kernel, cudaFuncAttributeMaxDynamicSharedMemorySize, GEMM_SM_BYTES);

    const int MROWS = BS;                   // 4704
    const int MT128 = (MROWS + 127) / 128;  // 37

    pos_kernel<<<BB * NN, 32>>>(perm, ppos);
    embed_kernel<<<BS, 256>>>(graph_emb, ppos, pnw, pnb, pew, peb, px);

    for (int l = 0; l < LL; l++) {
        const float* wq = Wq + (size_t)l * DD * 512;
        const float* wk = Wk + (size_t)l * DD * 512;
        const float* wv = Wv + (size_t)l * DD * 512;
        const float* wo = Wo + (size_t)l * 512 * DD;
        const float* w1 = W1 + (size_t)l * DD * FFD;
        const float* w2 = W2 + (size_t)l * FFD * DD;

        gemm_tf32_kernel<<<dim3(512 / 64, MT128), 256, GEMM_SM_BYTES>>>(px, wq, bq + l * 512, pq, MROWS, DD, 512, 0);
        gemm_tf32_kernel<<<dim3(512 / 64, MT128), 256, GEMM_SM_BYTES>>>(px, wk, bk + l * 512, pk, MROWS, DD, 512, 0);
        gemm_tf32_kernel<<<dim3(512 / 64, MT128), 256, GEMM_SM_BYTES>>>(px, wv, bv + l * 512, pv, MROWS, DD, 512, 0);

        attn_mma_kernel<<<dim3(QT2, HH, BB), 256, ATT_SM_BYTES>>>(pq, pk, pv, pat);

        gemm_tf32_kernel<<<dim3(DD / 64, MT128), 256, GEMM_SM_BYTES>>>(pat, wo, bo + l * DD, pt, MROWS, 512, DD, 0);
        add_ln_kernel<<<BS, 256>>>(px, pt, ln1g + l * DD, ln1b + l * DD);

        gemm_tf32_kernel<<<dim3(FFD / 64, MT128), 256, GEMM_SM_BYTES>>>(px, w1, b1 + l * FFD, pff, MROWS, DD, FFD, 1);
        gemm_tf32_kernel<<<dim3(DD / 64, MT128), 256, GEMM_SM_BYTES>>>(pff, w2, b2 + l * DD, pt, MROWS, FFD, DD, 0);
        add_ln_kernel<<<BS, 256>>>(px, pt, ln2g + l * DD, ln2b + l * DD);
    }

    float* out = (float*)d_out;
    node_out_kernel<<<BB * NN, 256>>>(px, now_, nob, out);
    edge_out_kernel<<<BB * NN * NN, 256>>>(px, eow, eob, out + BB * NN * NFD);
}

// round 10
// speedup vs baseline: 18.3900x; 1.0717x over previous
#include <cuda_runtime.h>
#include <cuda_bf16.h>
#include <math.h>
#include <stdint.h>

// Problem constants
#define BB 2
#define NN 48
#define DD 256
#define HH 8
#define DKV 64
#define FFD 1024
#define LL 4
#define PDD 32
#define NFD 20
#define NED 5
#define SS 2352           // NN + NN*NN
#define BS 4704           // BB*SS
#define BQ 128
#define QT2 ((SS + BQ - 1) / BQ)   // 19
#define NKT ((SS + 63) / 64)       // 37 key tiles

// -------------------- scratch (device globals; no allocation) --------------------
__device__ float g_pos[BB * NN * PDD];
__device__ float g_x[BS * DD];          // fp32 residual stream
__device__ float g_xr[BS * DD];         // tf32-rounded copy (GEMM A operand)
__device__ float g_q[BS * HH * DKV];
__device__ float g_k[BS * HH * DKV];
__device__ float g_v[BS * HH * DKV];
__device__ float g_attn[BS * HH * DKV];
__device__ float g_t[BS * DD];
__device__ float g_ff[BS * FFD];
// tf32-pre-rounded weights
__device__ float g_wq[LL * DD * 512];
__device__ float g_wk[LL * DD * 512];
__device__ float g_wv[LL * DD * 512];
__device__ float g_wo[LL * 512 * DD];
__device__ float g_w1[LL * DD * FFD];
__device__ float g_w2[LL * FFD * DD];

// -------------------- helpers --------------------
__device__ __forceinline__ float to_tf32(float x)
{
    uint32_t u;
    asm("cvt.rna.tf32.f32 %0, %1;" : "=r"(u) : "f"(x));
    return __uint_as_float(u);
}

__device__ __forceinline__ void mma_tf32(float* d, const uint32_t* a, const uint32_t* b)
{
    asm volatile(
        "mma.sync.aligned.m16n8k8.row.col.f32.tf32.tf32.f32 "
        "{%0,%1,%2,%3}, {%4,%5,%6,%7}, {%8,%9}, {%0,%1,%2,%3};"
        : "+f"(d[0]), "+f"(d[1]), "+f"(d[2]), "+f"(d[3])
        : "r"(a[0]), "r"(a[1]), "r"(a[2]), "r"(a[3]), "r"(b[0]), "r"(b[1]));
}

__device__ __forceinline__ void cp_async16(void* smem_dst, const void* gmem_src, bool valid)
{
    uint32_t s = (uint32_t)__cvta_generic_to_shared(smem_dst);
    int sz = valid ? 16 : 0;
    asm volatile("cp.async.cg.shared.global [%0], [%1], 16, %2;\n"
                 :: "r"(s), "l"(gmem_src), "r"(sz));
}

__device__ __forceinline__ void cp_commit() { asm volatile("cp.async.commit_group;\n" ::); }
__device__ __forceinline__ void cp_wait0()  { asm volatile("cp.async.wait_group 0;\n" ::); }

// -------------------- weight pre-round (fp32 -> tf32-rounded fp32) --------------------
__global__ void round4_kernel(const float4* __restrict__ src, float4* __restrict__ dst, int n4)
{
    int i = blockIdx.x * 256 + threadIdx.x;
    if (i >= n4) return;
    float4 v = src[i];
    dst[i] = make_float4(to_tf32(v.x), to_tf32(v.y), to_tf32(v.z), to_tf32(v.w));
}

// -------------------- pos = perm @ posenc --------------------
__global__ void pos_kernel(const float* __restrict__ perm, float* __restrict__ pos)
{
    int row = blockIdx.x;
    int d = threadIdx.x;
    const float* pr = perm + (size_t)row * NN;
    float freq = expf(-logf(10000.f) * (float)(d & ~1) / (float)PDD);
    float s = 0.f;
    #pragma unroll 8
    for (int j = 0; j < NN; j++) {
        float ang = (float)j * freq;
        float pe = (d & 1) ? cosf(ang) : sinf(ang);
        s += pr[j] * pe;
    }
    pos[row * PDD + d] = s;
}

// -------------------- token embedding: writes fp32 x and tf32 x_r --------------------
__global__ void embed_kernel(const float* __restrict__ ge, const float* __restrict__ pos,
                             const float* __restrict__ pnw, const float* __restrict__ pnb,
                             const float* __restrict__ pew, const float* __restrict__ peb,
                             float* __restrict__ x, float* __restrict__ xr)
{
    int tok = blockIdx.x;
    int b = tok / SS;
    int r = tok % SS;
    int d = threadIdx.x;
    __shared__ float pi[PDD];
    __shared__ float pj[PDD];

    float s;
    if (r < NN) {
        if (d < PDD) pi[d] = pos[(b * NN + r) * PDD + d];
        __syncthreads();
        s = ge[b * DD + d] + pnb[d];
        #pragma unroll
        for (int p = 0; p < PDD; p++) s += pi[p] * pnw[p * DD + d];
    } else {
        int e = r - NN;
        int i = e / NN, j = e % NN;
        if (d < PDD) pi[d] = pos[(b * NN + i) * PDD + d];
        else if (d < 2 * PDD) pj[d - PDD] = pos[(b * NN + j) * PDD + (d - PDD)];
        __syncthreads();
        s = ge[b * DD + d] + peb[d];
        #pragma unroll
        for (int p = 0; p < PDD; p++) s += pi[p] * pew[p * DD + d];
        #pragma unroll
        for (int p = 0; p < PDD; p++) s += pj[p] * pew[(PDD + p) * DD + d];
    }
    x[(size_t)tok * DD + d] = s;
    xr[(size_t)tok * DD + d] = to_tf32(s);
}

// -------------------- tf32 GEMM, cp.async double-buffered, templated BM --------------------
// 256 threads (8 warps). BM=128: warps 4x2, warp 32x32, NFR=4.
//                        BM=64 : warps 2x4, warp 32x16, NFR=2.
// All operands pre-rounded to tf32 upstream -> no cvt in mainloop.
template<int BM>
__global__ __launch_bounds__(256) void gemm_tf32_kernel(
    const float* __restrict__ A, const float* __restrict__ W,
    const float* __restrict__ bias, float* __restrict__ C,
    int M, int K, int N, int relu, int rnd)
{
    constexpr int WN  = (BM == 128) ? 2 : 4;    // warp cols
    constexpr int NFR = (BM == 128) ? 4 : 2;    // n-fragments per warp
    constexpr int WARP_N = 64 / WN;
    constexpr int TPR = 256 / BM;               // threads per A row
    constexpr int AFL = 32 / TPR;               // floats per thread (A row chunk)

    extern __shared__ float smg[];
    float (*As)[36] = (float(*)[36])smg;                    // [2*BM][36]
    float (*Bs)[72] = (float(*)[72])(smg + 2 * BM * 36);    // [2*32][72]

    int tid = threadIdx.x;
    int warp = tid >> 5, lane = tid & 31;
    int g = lane >> 2, t = lane & 3;
    int wm = warp / WN, wn = warp % WN;
    int m0 = wm * 32;
    int n0w = wn * WARP_N;
    int brow0 = blockIdx.y * BM;
    int bcol0 = blockIdx.x * 64;

    float acc[2][NFR][4];
    #pragma unroll
    for (int mi = 0; mi < 2; mi++)
        #pragma unroll
        for (int ni = 0; ni < NFR; ni++)
            #pragma unroll
            for (int v = 0; v < 4; v++) acc[mi][ni][v] = 0.f;

    int a_row = tid / TPR;
    int a_cb  = (tid % TPR) * AFL;
    int grow  = brow0 + a_row;
    bool a_ok = grow < M;
    const float* a_src = A + (size_t)(a_ok ? grow : 0) * K;
    int nk = K >> 5;

    // prologue: tile 0 -> buffer 0
    {
        #pragma unroll
        for (int i = 0; i < AFL / 4; i++)
            cp_async16(&As[a_row][a_cb + i * 4], a_src + a_cb + i * 4, a_ok);
        #pragma unroll
        for (int i = 0; i < 2; i++) {
            int lin = tid * 2 + i;
            int br = lin >> 4;
            int c = (lin & 15) * 4;
            cp_async16(&Bs[br][c], W + (size_t)br * N + bcol0 + c, true);
        }
        cp_commit();
    }

    for (int kt = 0; kt < nk; kt++) {
        cp_wait0();
        __syncthreads();

        if (kt + 1 < nk) {
            int k0 = (kt + 1) << 5;
            int nb = ((kt + 1) & 1);
            #pragma unroll
            for (int i = 0; i < AFL / 4; i++)
                cp_async16(&As[nb * BM + a_row][a_cb + i * 4], a_src + k0 + a_cb + i * 4, a_ok);
            #pragma unroll
            for (int i = 0; i < 2; i++) {
                int lin = tid * 2 + i;
                int br = lin >> 4;
                int c = (lin & 15) * 4;
                cp_async16(&Bs[nb * 32 + br][c], W + (size_t)(k0 + br) * N + bcol0 + c, true);
            }
            cp_commit();
        }

        const float (*Ac)[36] = As + (kt & 1) * BM;
        const float (*Bc)[72] = Bs + (kt & 1) * 32;
        #pragma unroll
        for (int k8 = 0; k8 < 4; k8++) {
            int kk = k8 * 8;
            uint32_t afr[2][4];
            #pragma unroll
            for (int mi = 0; mi < 2; mi++) {
                int row = m0 + mi * 16;
                afr[mi][0] = __float_as_uint(Ac[row + g][kk + t]);
                afr[mi][1] = __float_as_uint(Ac[row + g + 8][kk + t]);
                afr[mi][2] = __float_as_uint(Ac[row + g][kk + t + 4]);
                afr[mi][3] = __float_as_uint(Ac[row + g + 8][kk + t + 4]);
            }
            uint32_t bfr[NFR][2];
            #pragma unroll
            for (int ni = 0; ni < NFR; ni++) {
                int col = n0w + ni * 8;
                bfr[ni][0] = __float_as_uint(Bc[kk + t][col + g]);
                bfr[ni][1] = __float_as_uint(Bc[kk + t + 4][col + g]);
            }
            #pragma unroll
            for (int mi = 0; mi < 2; mi++)
                #pragma unroll
                for (int ni = 0; ni < NFR; ni++)
                    mma_tf32(acc[mi][ni], afr[mi], bfr[ni]);
        }
    }

    // epilogue
    #pragma unroll
    for (int ni = 0; ni < NFR; ni++) {
        int col = bcol0 + n0w + ni * 8 + 2 * t;
        float b0 = bias[col], b1 = bias[col + 1];
        #pragma unroll
        for (int mi = 0; mi < 2; mi++) {
            int row = brow0 + m0 + mi * 16 + g;
            float v0 = acc[mi][ni][0] + b0;
            float v1 = acc[mi][ni][1] + b1;
            float v2 = acc[mi][ni][2] + b0;
            float v3 = acc[mi][ni][3] + b1;
            if (relu) {
                v0 = fmaxf(v0, 0.f); v1 = fmaxf(v1, 0.f);
                v2 = fmaxf(v2, 0.f); v3 = fmaxf(v3, 0.f);
            }
            if (rnd) {
                v0 = to_tf32(v0); v1 = to_tf32(v1);
                v2 = to_tf32(v2); v3 = to_tf32(v3);
            }
            if (row < M)     { float2 p = make_float2(v0, v1); *(float2*)(C + (size_t)row * N + col) = p; }
            if (row + 8 < M) { float2 p = make_float2(v2, v3); *(float2*)(C + (size_t)(row + 8) * N + col) = p; }
        }
    }
}

// -------------------- tf32 flash attention --------------------
// grid (QT2, HH, BB), 256 thr (8 warps). BQ=128 q-tile, 64-key tiles,
// cp.async double-buffered K/V (pre-rounded tf32), register softmax,
// shuffle-built P fragments. No cvt in mainloop except P rounding.
#define ATT_SM_FLOATS (128 * 68 + 2 * 64 * 68 + 2 * 64 * 72)
#define ATT_SM_BYTES (ATT_SM_FLOATS * 4)

__global__ __launch_bounds__(256, 2) void attn_mma_kernel(
    const float* __restrict__ Q, const float* __restrict__ Kmat,
    const float* __restrict__ V, float* __restrict__ O)
{
    extern __shared__ float sm[];
    float (*Qs)[68] = (float(*)[68])sm;                          // 128x68
    float (*Ks)[68] = (float(*)[68])(sm + 128 * 68);             // [2*64][68]
    float (*Vs)[72] = (float(*)[72])(sm + 128 * 68 + 2 * 64 * 68); // [2*64][72]

    int b = blockIdx.z, h = blockIdx.y;
    int q0 = blockIdx.x * BQ;
    int tid = threadIdx.x;
    int warp = tid >> 5, lane = tid & 31;
    int g = lane >> 2, t = lane & 3;
    int mrow = warp * 16;

    const float* Qb = Q + (size_t)b * SS * 512 + h * 64;
    const float* Kb = Kmat + (size_t)b * SS * 512 + h * 64;
    const float* Vb = V + (size_t)b * SS * 512 + h * 64;

    int kv_row = tid >> 2;
    int kv_cb  = (tid & 3) * 16;

    // prologue: issue K/V tile 0 into buffer 0
    {
        bool ok = kv_row < SS;
        const float* ks = Kb + (size_t)(ok ? kv_row : 0) * 512 + kv_cb;
        const float* vs = Vb + (size_t)(ok ? kv_row : 0) * 512 + kv_cb;
        #pragma unroll
        for (int i = 0; i < 4; i++) {
            cp_async16(&Ks[kv_row][kv_cb + i * 4], ks + i * 4, ok);
            cp_async16(&Vs[kv_row][kv_cb + i * 4], vs + i * 4, ok);
        }
        cp_commit();
    }

    // stage Q (scaled by 1/sqrt(64); exact power of 2, operand pre-rounded)
    {
        int r = tid >> 1;
        int cb = (tid & 1) * 32;
        #pragma unroll
        for (int i = 0; i < 8; i++) {
            int c = cb + i * 4;
            float4 v = make_float4(0.f, 0.f, 0.f, 0.f);
            if (q0 + r < SS) v = *(const float4*)(Qb + (size_t)(q0 + r) * 512 + c);
            float4 w;
            w.x = v.x * 0.125f; w.y = v.y * 0.125f;
            w.z = v.z * 0.125f; w.w = v.w * 0.125f;
            *(float4*)&Qs[r][c] = w;
        }
    }

    float m0 = -1e30f, m1 = -1e30f, l0 = 0.f, l1 = 0.f;
    float accO[8][4];
    #pragma unroll
    for (int ni = 0; ni < 8; ni++)
        #pragma unroll
        for (int v = 0; v < 4; v++) accO[ni][v] = 0.f;

    int srcA = (lane & ~3) | (t >> 1);
    int srcB = srcA + 2;
    bool odd = (t & 1);

    for (int kt = 0; kt < NKT; kt++) {
        int kt0 = kt * 64;
        cp_wait0();
        __syncthreads();

        if (kt + 1 < NKT) {
            int nb = (kt + 1) & 1;
            int grow = kt0 + 64 + kv_row;
            bool ok = grow < SS;
            const float* ks = Kb + (size_t)(ok ? grow : 0) * 512 + kv_cb;
            const float* vs = Vb + (size_t)(ok ? grow : 0) * 512 + kv_cb;
            #pragma unroll
            for (int i = 0; i < 4; i++) {
                cp_async16(&Ks[nb * 64 + kv_row][kv_cb + i * 4], ks + i * 4, ok);
                cp_async16(&Vs[nb * 64 + kv_row][kv_cb + i * 4], vs + i * 4, ok);
            }
            cp_commit();
        }

        const float (*Kc)[68] = Ks + (kt & 1) * 64;
        const float (*Vc)[72] = Vs + (kt & 1) * 64;

        // ---- S = Q @ K^T ----
        float accS[8][4];
        #pragma unroll
        for (int ni = 0; ni < 8; ni++)
            #pragma unroll
            for (int v = 0; v < 4; v++) accS[ni][v] = 0.f;

        #pragma unroll
        for (int k8 = 0; k8 < 8; k8++) {
            int kk = k8 * 8;
            uint32_t afr[4];
            afr[0] = __float_as_uint(Qs[mrow + g][kk + t]);
            afr[1] = __float_as_uint(Qs[mrow + g + 8][kk + t]);
            afr[2] = __float_as_uint(Qs[mrow + g][kk + t + 4]);
            afr[3] = __float_as_uint(Qs[mrow + g + 8][kk + t + 4]);
            #pragma unroll
            for (int ni = 0; ni < 8; ni++) {
                uint32_t bfr[2];
                bfr[0] = __float_as_uint(Kc[ni * 8 + g][kk + t]);
                bfr[1] = __float_as_uint(Kc[ni * 8 + g][kk + t + 4]);
                mma_tf32(accS[ni], afr, bfr);
            }
        }

        // tail masking (only last tile)
        if (kt0 + 64 > SS) {
            #pragma unroll
            for (int ni = 0; ni < 8; ni++) {
                int c0 = kt0 + ni * 8 + 2 * t;
                if (c0 >= SS)     { accS[ni][0] = -1e30f; accS[ni][2] = -1e30f; }
                if (c0 + 1 >= SS) { accS[ni][1] = -1e30f; accS[ni][3] = -1e30f; }
            }
        }

        // ---- register online softmax (rows g and g+8; 4 lanes per row) ----
        float rx0 = -1e30f, rx1 = -1e30f;
        #pragma unroll
        for (int ni = 0; ni < 8; ni++) {
            rx0 = fmaxf(rx0, fmaxf(accS[ni][0], accS[ni][1]));
            rx1 = fmaxf(rx1, fmaxf(accS[ni][2], accS[ni][3]));
        }
        rx0 = fmaxf(rx0, __shfl_xor_sync(0xffffffffu, rx0, 1));
        rx0 = fmaxf(rx0, __shfl_xor_sync(0xffffffffu, rx0, 2));
        rx1 = fmaxf(rx1, __shfl_xor_sync(0xffffffffu, rx1, 1));
        rx1 = fmaxf(rx1, __shfl_xor_sync(0xffffffffu, rx1, 2));

        float mn0 = fmaxf(m0, rx0), mn1 = fmaxf(m1, rx1);
        float cr0 = __expf(m0 - mn0), cr1 = __expf(m1 - mn1);
        float rs0 = 0.f, rs1 = 0.f;
        #pragma unroll
        for (int ni = 0; ni < 8; ni++) {
            float p0 = __expf(accS[ni][0] - mn0);
            float p1 = __expf(accS[ni][1] - mn0);
            float p2 = __expf(accS[ni][2] - mn1);
            float p3 = __expf(accS[ni][3] - mn1);
            rs0 += p0 + p1;
            rs1 += p2 + p3;
            accS[ni][0] = to_tf32(p0);
            accS[ni][1] = to_tf32(p1);
            accS[ni][2] = to_tf32(p2);
            accS[ni][3] = to_tf32(p3);
        }
        rs0 += __shfl_xor_sync(0xffffffffu, rs0, 1);
        rs0 += __shfl_xor_sync(0xffffffffu, rs0, 2);
        rs1 += __shfl_xor_sync(0xffffffffu, rs1, 1);
        rs1 += __shfl_xor_sync(0xffffffffu, rs1, 2);
        l0 = l0 * cr0 + rs0;
        l1 = l1 * cr1 + rs1;
        m0 = mn0; m1 = mn1;
        #pragma unroll
        for (int ni = 0; ni < 8; ni++) {
            accO[ni][0] *= cr0; accO[ni][1] *= cr0;
            accO[ni][2] *= cr1; accO[ni][3] *= cr1;
        }

        // ---- O += P @ V, P fragments built via shuffles from accS ----
        #pragma unroll
        for (int k8 = 0; k8 < 8; k8++) {
            int kk = k8 * 8;
            float c0a = __shfl_sync(0xffffffffu, accS[k8][0], srcA);
            float c1a = __shfl_sync(0xffffffffu, accS[k8][1], srcA);
            float c2a = __shfl_sync(0xffffffffu, accS[k8][2], srcA);
            float c3a = __shfl_sync(0xffffffffu, accS[k8][3], srcA);
            float c0b = __shfl_sync(0xffffffffu, accS[k8][0], srcB);
            float c1b = __shfl_sync(0xffffffffu, accS[k8][1], srcB);
            float c2b = __shfl_sync(0xffffffffu, accS[k8][2], srcB);
            float c3b = __shfl_sync(0xffffffffu, accS[k8][3], srcB);
            uint32_t afr[4];
            afr[0] = __float_as_uint(odd ? c1a : c0a);
            afr[1] = __float_as_uint(odd ? c3a : c2a);
            afr[2] = __float_as_uint(odd ? c1b : c0b);
            afr[3] = __float_as_uint(odd ? c3b : c2b);
            #pragma unroll
            for (int ni = 0; ni < 8; ni++) {
                uint32_t bfr[2];
                bfr[0] = __float_as_uint(Vc[kk + t][ni * 8 + g]);
                bfr[1] = __float_as_uint(Vc[kk + t + 4][ni * 8 + g]);
                mma_tf32(accO[ni], afr, bfr);
            }
        }
    }

    // store O / l (tf32-rounded: feeds Wo GEMM as A operand only)
    float* Ob = O + (size_t)b * SS * 512 + h * 64;
    float inv0 = 1.f / l0, inv1 = 1.f / l1;
    int r1 = q0 + mrow + g;
    int r2 = r1 + 8;
    #pragma unroll
    for (int ni = 0; ni < 8; ni++) {
        int col = ni * 8 + 2 * t;
        if (r1 < SS) {
            float2 p = make_float2(to_tf32(accO[ni][0] * inv0), to_tf32(accO[ni][1] * inv0));
            *(float2*)(Ob + (size_t)r1 * 512 + col) = p;
        }
        if (r2 < SS) {
            float2 p = make_float2(to_tf32(accO[ni][2] * inv1), to_tf32(accO[ni][3] * inv1));
            *(float2*)(Ob + (size_t)r2 * 512 + col) = p;
        }
    }
}

// -------------------- x = LayerNorm(x + h): writes fp32 x and tf32 x_r --------------------
__global__ void add_ln_kernel(float* __restrict__ x, float* __restrict__ xr,
                              const float* __restrict__ h,
                              const float* __restrict__ g, const float* __restrict__ bb)
{
    int row = blockIdx.x, t = threadIdx.x;
    float v = x[(size_t)row * DD + t] + h[(size_t)row * DD + t];
    float s1 = v, s2 = v * v;
    #pragma unroll
    for (int o = 16; o; o >>= 1) {
        s1 += __shfl_xor_sync(0xffffffffu, s1, o);
        s2 += __shfl_xor_sync(0xffffffffu, s2, o);
    }
    __shared__ float r1[8], r2[8];
    int w = t >> 5, ln = t & 31;
    if (ln == 0) { r1[w] = s1; r2[w] = s2; }
    __syncthreads();
    if (w == 0) {
        float a = (ln < 8) ? r1[ln] : 0.f;
        float c = (ln < 8) ? r2[ln] : 0.f;
        #pragma unroll
        for (int o = 4; o; o >>= 1) {
            a += __shfl_xor_sync(0xffffffffu, a, o);
            c += __shfl_xor_sync(0xffffffffu, c, o);
        }
        if (ln == 0) { r1[0] = a; r2[0] = c; }
    }
    __syncthreads();
    float mean = r1[0] * (1.f / 256.f);
    float var = r2[0] * (1.f / 256.f) - mean * mean;
    float rstd = rsqrtf(var + 1e-5f);
    float out = (v - mean) * rstd * g[t] + bb[t];
    x[(size_t)row * DD + t] = out;
    xr[(size_t)row * DD + t] = to_tf32(out);
}

// -------------------- output heads (read fp32 x) --------------------
__global__ void node_out_kernel(const float* __restrict__ x, const float* __restrict__ w,
                                const float* __restrict__ bias, float* __restrict__ out)
{
    int idx = blockIdx.x;
    int b = idx / NN, i = idx % NN;
    int t = threadIdx.x;
    __shared__ float xr[DD];
    xr[t] = x[(size_t)(b * SS + i) * DD + t];
    __syncthreads();
    int wrp = t >> 5, ln = t & 31;
    #pragma unroll
    for (int cb = 0; cb < 24; cb += 8) {
        int c = cb + wrp;
        float s = 0.f;
        if (c < NFD) {
            #pragma unroll
            for (int k = 0; k < 8; k++) s += xr[ln + 32 * k] * w[(ln + 32 * k) * NFD + c];
        }
        #pragma unroll
        for (int o = 16; o; o >>= 1) s += __shfl_xor_sync(0xffffffffu, s, o);
        if (ln == 0 && c < NFD) out[(size_t)idx * NFD + c] = s + bias[c];
    }
}

__global__ void edge_out_kernel(const float* __restrict__ x, const float* __restrict__ w,
                                const float* __restrict__ bias, float* __restrict__ out)
{
    int idx = blockIdx.x;
    int b = idx / (NN * NN);
    int r = idx % (NN * NN);
    int i = r / NN, j = r % NN;
    int t = threadIdx.x;
    __shared__ float sr[DD];
    const float* xi = x + (size_t)(b * SS + NN + i * NN + j) * DD;
    const float* xj = x + (size_t)(b * SS + NN + j * NN + i) * DD;
    sr[t] = xi[t] + xj[t];
    __syncthreads();
    int wrp = t >> 5, ln = t & 31;
    int c = wrp;
    float s = 0.f;
    if (c < NED) {
        #pragma unroll
        for (int k = 0; k < 8; k++) s += sr[ln + 32 * k] * w[(ln + 32 * k) * NED + c];
    }
    #pragma unroll
    for (int o = 16; o; o >>= 1) s += __shfl_xor_sync(0xffffffffu, s, o);
    if (ln == 0 && c < NED) out[(size_t)idx * NED + c] = 0.5f * s + bias[c];
}

// -------------------- host orchestration --------------------
static inline float* sym_addr(const void* sym)
{
    void* p = nullptr;
    cudaGetSymbolAddress(&p, sym);
    return (float*)p;
}

#define GEMM_SM128 ((2 * 128 * 36 + 2 * 32 * 72) * 4)
#define GEMM_SM64  ((2 * 64 * 36 + 2 * 32 * 72) * 4)

extern "C" void kernel_launch(void* const* d_in, const int* in_sizes, int n_in,
                              void* d_out, int out_size)
{
    (void)in_sizes; (void)n_in; (void)out_size;
    const float* graph_emb = (const float*)d_in[0];
    const float* perm      = (const float*)d_in[1];
    const float* pnw = (const float*)d_in[3];
    const float* pnb = (const float*)d_in[4];
    const float* pew = (const float*)d_in[5];
    const float* peb = (const float*)d_in[6];
    const float* now_ = (const float*)d_in[7];
    const float* nob = (const float*)d_in[8];
    const float* eow = (const float*)d_in[9];
    const float* eob = (const float*)d_in[10];
    const float* Wq = (const float*)d_in[11];
    const float* bq = (const float*)d_in[12];
    const float* Wk = (const float*)d_in[13];
    const float* bk = (const float*)d_in[14];
    const float* Wv = (const float*)d_in[15];
    const float* bv = (const float*)d_in[16];
    const float* Wo = (const float*)d_in[17];
    const float* bo = (const float*)d_in[18];
    const float* W1 = (const float*)d_in[19];
    const float* b1 = (const float*)d_in[20];
    const float* W2 = (const float*)d_in[21];
    const float* b2 = (const float*)d_in[22];
    const float* ln1g = (const float*)d_in[23];
    const float* ln1b = (const float*)d_in[24];
    const float* ln2g = (const float*)d_in[25];
    const float* ln2b = (const float*)d_in[26];

    float* px   = sym_addr(g_x);
    float* pxr  = sym_addr(g_xr);
    float* ppos = sym_addr(g_pos);
    float* pq   = sym_addr(g_q);
    float* pk   = sym_addr(g_k);
    float* pv   = sym_addr(g_v);
    float* pat  = sym_addr(g_attn);
    float* pt   = sym_addr(g_t);
    float* pff  = sym_addr(g_ff);
    float* pwq  = sym_addr(g_wq);
    float* pwk  = sym_addr(g_wk);
    float* pwv  = sym_addr(g_wv);
    float* pwo  = sym_addr(g_wo);
    float* pw1  = sym_addr(g_w1);
    float* pw2  = sym_addr(g_w2);

    cudaFuncSetAttribute(attn_mma_kernel, cudaFuncAttributeMaxDynamicSharedMemorySize, ATT_SM_BYTES);
    cudaFuncSetAttribute(gemm_tf32_kernel<128>, cudaFuncAttributeMaxDynamicSharedMemorySize, GEMM_SM128);
    cudaFuncSetAttribute(gemm_tf32_kernel<64>, cudaFuncAttributeMaxDynamicSharedMemorySize, GEMM_SM64);

    const int MROWS = BS;                   // 4704
    const int MT128 = (MROWS + 127) / 128;  // 37
    const int MT64  = (MROWS + 63) / 64;    // 74

    // pre-round weights to tf32 scratch
    {
        int nqkv = LL * DD * 512 / 4;       // float4 count
        int nff  = LL * DD * FFD / 4;
        round4_kernel<<<(nqkv + 255) / 256, 256>>>((const float4*)Wq, (float4*)pwq, nqkv);
        round4_kernel<<<(nqkv + 255) / 256, 256>>>((const float4*)Wk, (float4*)pwk, nqkv);
        round4_kernel<<<(nqkv + 255) / 256, 256>>>((const float4*)Wv, (float4*)pwv, nqkv);
        round4_kernel<<<(nqkv + 255) / 256, 256>>>((const float4*)Wo, (float4*)pwo, nqkv);
        round4_kernel<<<(nff + 255) / 256, 256>>>((const float4*)W1, (float4*)pw1, nff);
        round4_kernel<<<(nff + 255) / 256, 256>>>((const float4*)W2, (float4*)pw2, nff);
    }

    pos_kernel<<<BB * NN, 32>>>(perm, ppos);
    embed_kernel<<<BS, 256>>>(graph_emb, ppos, pnw, pnb, pew, peb, px, pxr);

    for (int l = 0; l < LL; l++) {
        const float* wq = pwq + (size_t)l * DD * 512;
        const float* wk = pwk + (size_t)l * DD * 512;
        const float* wv = pwv + (size_t)l * DD * 512;
        const float* wo = pwo + (size_t)l * 512 * DD;
        const float* w1 = pw1 + (size_t)l * DD * FFD;
        const float* w2 = pw2 + (size_t)l * FFD * DD;

        gemm_tf32_kernel<128><<<dim3(512 / 64, MT128), 256, GEMM_SM128>>>(pxr, wq, bq + l * 512, pq, MROWS, DD, 512, 0, 1);
        gemm_tf32_kernel<128><<<dim3(512 / 64, MT128), 256, GEMM_SM128>>>(pxr, wk, bk + l * 512, pk, MROWS, DD, 512, 0, 1);
        gemm_tf32_kernel<128><<<dim3(512 / 64, MT128), 256, GEMM_SM128>>>(pxr, wv, bv + l * 512, pv, MROWS, DD, 512, 0, 1);

        attn_mma_kernel<<<dim3(QT2, HH, BB), 256, ATT_SM_BYTES>>>(pq, pk, pv, pat);

        gemm_tf32_kernel<64><<<dim3(DD / 64, MT64), 256, GEMM_SM64>>>(pat, wo, bo + l * DD, pt, MROWS, 512, DD, 0, 0);
        add_ln_kernel<<<BS, 256>>>(px, pxr, pt, ln1g + l * DD, ln1b + l * DD);

        gemm_tf32_kernel<128><<<dim3(FFD / 64, MT128), 256, GEMM_SM128>>>(pxr, w1, b1 + l * FFD, pff, MROWS, DD, FFD, 1, 1);
        gemm_tf32_kernel<64><<<dim3(DD / 64, MT64), 256, GEMM_SM64>>>(pff, w2, b2 + l * DD, pt, MROWS, FFD, DD, 0, 0);
        add_ln_kernel<<<BS, 256>>>(px, pxr, pt, ln2g + l * DD, ln2b + l * DD);
    }

    float* out = (float*)d_out;
    node_out_kernel<<<BB * NN, 256>>>(px, now_, nob, out);
    edge_out_kernel<<<BB * NN * NN, 256>>>(px, eow, eob, out + BB * NN * NFD);
}